// round 1
// baseline (speedup 1.0000x reference)
#include <cuda_runtime.h>
#include <cuda_bf16.h>

// ---------------------------------------------------------------------------
// ASLRNN3: only the last frame feeds outs[-1]; hidden recurrence is affine and
// input-independent of i2h. Pipeline (N = 512 batch, last frame only):
//   hand conv+pool -> feat (1024,304)
//   fc GEMM -> both (1024,300)  [rows 0..511 = left, 512..1023 = right]
//   conv2+relu+maxpool3 -> y (512,9504)
//   l2 GEMM (split-K) -> i2h (512,500)
//   affine doubling: (W,b) -> (W^32, c) on 512-padded buffers
//   hidden = h0 @ (W^32)^T + c  -> d_out[5120..]
//   out = relu((i2h + hidden) @ out_w^T + out_b) -> d_out[0..5119]
// ---------------------------------------------------------------------------

#define NB 512          // batch
#define FEAT 304
#define HF 300
#define YK 9504
#define HID 500
#define HIDP 512        // padded hidden dim
#define OUT 10

// ---- scratch (device globals; no allocations allowed) ----
__device__ float g_feat[1024 * FEAT];
__device__ float g_both[1024 * HF];
__device__ float g_y[NB * YK];
__device__ float g_i2h[NB * HID];
__device__ float g_part[4 * NB * HID];
__device__ float g_Wpad[HIDP * HIDP];
__device__ float g_h0pad[NB * HIDP];
__device__ float g_M0[HIDP * HIDP];
__device__ float g_M1[HIDP * HIDP];
__device__ float g_cv0[HIDP];
__device__ float g_cv1[HIDP];
__device__ float g_hid[NB * HID];

// ---------------------------------------------------------------------------
// Generic tiled SGEMM: C(M,N) = A(M,K) * op(B) [+bias] [relu]
//  TRANSB=true : B is (N,K) row-major  (torch-Linear pattern, A @ B^T)
//  TRANSB=false: B is (K,N) row-major  (plain A @ B)
//  SPLIT=true  : gridDim.z split-K, writes partials (no bias/relu)
// Requirements: M % 64 == 0, K % 16 == 0 (per split chunk), lda/ldb % 4 == 0.
// N edge handled by guards.
// ---------------------------------------------------------------------------
#define BM 64
#define BN 64
#define BK 16

template<bool TRANSB, bool RELU, bool SPLIT>
__global__ __launch_bounds__(256)
void gemm_kernel(int M, int N, int K,
                 const float* __restrict__ A, int lda,
                 const float* __restrict__ B, int ldb,
                 const float* __restrict__ bias,
                 float* __restrict__ C, int ldc, int splitLen)
{
    __shared__ float As[BK][BM];
    __shared__ float Bs[BK][BN + 4];

    const int tid = threadIdx.x;
    const int tx = tid & 15;
    const int ty = tid >> 4;
    const int m0 = blockIdx.y * BM;
    const int n0 = blockIdx.x * BN;

    int kbeg = 0, kend = K;
    if (SPLIT) {
        kbeg = blockIdx.z * splitLen;
        kend = min(K, kbeg + splitLen);
        C += (size_t)blockIdx.z * (size_t)M * (size_t)ldc;
    }

    float acc[4][4] = {};

    const int ar  = tid >> 2;        // 0..63
    const int ac4 = (tid & 3) * 4;   // 0,4,8,12

    for (int k0 = kbeg; k0 < kend; k0 += BK) {
        // ---- A tile: As[k][m]
        {
            const float4 av = *reinterpret_cast<const float4*>(
                &A[(size_t)(m0 + ar) * lda + k0 + ac4]);
            As[ac4 + 0][ar] = av.x;
            As[ac4 + 1][ar] = av.y;
            As[ac4 + 2][ar] = av.z;
            As[ac4 + 3][ar] = av.w;
        }
        // ---- B tile: Bs[k][n]
        if (TRANSB) {
            const int bn  = tid >> 2;
            const int bc4 = (tid & 3) * 4;
            float4 bv = make_float4(0.f, 0.f, 0.f, 0.f);
            if (n0 + bn < N)
                bv = *reinterpret_cast<const float4*>(
                    &B[(size_t)(n0 + bn) * ldb + k0 + bc4]);
            Bs[bc4 + 0][bn] = bv.x;
            Bs[bc4 + 1][bn] = bv.y;
            Bs[bc4 + 2][bn] = bv.z;
            Bs[bc4 + 3][bn] = bv.w;
        } else {
            const int bk  = tid >> 4;         // 0..15
            const int bn4 = (tid & 15) * 4;   // 0..60
            float4 bv;
            if (n0 + bn4 + 3 < N) {
                bv = *reinterpret_cast<const float4*>(
                    &B[(size_t)(k0 + bk) * ldb + n0 + bn4]);
            } else {
                float t0 = (n0 + bn4 + 0 < N) ? B[(size_t)(k0 + bk) * ldb + n0 + bn4 + 0] : 0.f;
                float t1 = (n0 + bn4 + 1 < N) ? B[(size_t)(k0 + bk) * ldb + n0 + bn4 + 1] : 0.f;
                float t2 = (n0 + bn4 + 2 < N) ? B[(size_t)(k0 + bk) * ldb + n0 + bn4 + 2] : 0.f;
                float t3 = (n0 + bn4 + 3 < N) ? B[(size_t)(k0 + bk) * ldb + n0 + bn4 + 3] : 0.f;
                bv = make_float4(t0, t1, t2, t3);
            }
            Bs[bk][bn4 + 0] = bv.x;
            Bs[bk][bn4 + 1] = bv.y;
            Bs[bk][bn4 + 2] = bv.z;
            Bs[bk][bn4 + 3] = bv.w;
        }
        __syncthreads();

        #pragma unroll
        for (int kk = 0; kk < BK; ++kk) {
            float a[4], b[4];
            #pragma unroll
            for (int i = 0; i < 4; ++i) a[i] = As[kk][ty * 4 + i];
            #pragma unroll
            for (int j = 0; j < 4; ++j) b[j] = Bs[kk][tx * 4 + j];
            #pragma unroll
            for (int i = 0; i < 4; ++i)
                #pragma unroll
                for (int j = 0; j < 4; ++j)
                    acc[i][j] = fmaf(a[i], b[j], acc[i][j]);
        }
        __syncthreads();
    }

    #pragma unroll
    for (int i = 0; i < 4; ++i) {
        const int row = m0 + ty * 4 + i;
        #pragma unroll
        for (int j = 0; j < 4; ++j) {
            const int col = n0 + tx * 4 + j;
            if (col < N) {
                float v = acc[i][j];
                if (!SPLIT) {
                    if (bias) v += bias[col];
                    if (RELU) v = fmaxf(v, 0.f);
                }
                C[(size_t)row * ldc + col] = v;
            }
        }
    }
}

// ---------------------------------------------------------------------------
__global__ void splitk_reduce(const float* __restrict__ part,
                              const float* __restrict__ bias,
                              float* __restrict__ C, int M, int N, int S)
{
    int idx = blockIdx.x * blockDim.x + threadIdx.x;
    if (idx >= M * N) return;
    int n = idx % N;
    float v = bias ? bias[n] : 0.f;
    for (int s = 0; s < S; ++s) v += part[(size_t)s * M * N + idx];
    C[idx] = v;
}

// ---------------------------------------------------------------------------
// Pad W -> (512,512), h0 -> (512,512 cols), init c0 = padded bias
__global__ void pad_kernel(const float* __restrict__ W,
                           const float* __restrict__ b,
                           const float* __restrict__ h0)
{
    int idx = blockIdx.x * blockDim.x + threadIdx.x;
    if (idx >= HIDP * HIDP) return;
    int r = idx >> 9, c = idx & (HIDP - 1);
    g_Wpad[idx]  = (r < HID && c < HID) ? W[r * HID + c] : 0.f;
    g_h0pad[idx] = (c < HID) ? h0[r * HID + c] : 0.f;
    if (idx < HIDP) g_cv0[idx] = (idx < HID) ? b[idx] : 0.f;
}

// c_new[j] = c[j] + sum_i c[i] * M[j][i]   (M is 512x512 padded)
__global__ void vec_affine(const float* __restrict__ c,
                           const float* __restrict__ Mm,
                           float* __restrict__ cnew)
{
    int wid  = (blockIdx.x * blockDim.x + threadIdx.x) >> 5;
    int lane = threadIdx.x & 31;
    if (wid >= HIDP) return;
    float s = 0.f;
    for (int i = lane; i < HIDP; i += 32) s += c[i] * Mm[wid * HIDP + i];
    #pragma unroll
    for (int o = 16; o; o >>= 1) s += __shfl_down_sync(0xffffffffu, s, o);
    if (lane == 0) cnew[wid] = c[wid] + s;
}

// ---------------------------------------------------------------------------
// hand branch: conv1d(k=2, 2->16ch) + relu + maxpool2 -> feat (per sample, 304)
__global__ void hand_feat_kernel(const float* __restrict__ hd,
                                 const float* __restrict__ lcw, const float* __restrict__ lcb,
                                 const float* __restrict__ rcw, const float* __restrict__ rcb,
                                 int tOff)
{
    const int s    = blockIdx.x;      // 0..1023
    const int n    = s & (NB - 1);
    const int hand = s >> 9;
    const float* x  = hd + tOff + n * 84 + hand * 42;
    const float* cw = hand ? rcw : lcw;
    const float* cb = hand ? rcb : lcb;

    __shared__ float xs[42];
    __shared__ float z[16 * 20];
    const int tid = threadIdx.x;
    if (tid < 42) xs[tid] = x[tid];
    __syncthreads();

    for (int idx = tid; idx < 320; idx += 128) {
        int o = idx / 20, j = idx % 20;
        float v = cb[o]
                + cw[o * 4 + 0] * xs[2 * j]
                + cw[o * 4 + 1] * xs[2 * j + 2]
                + cw[o * 4 + 2] * xs[2 * j + 1]
                + cw[o * 4 + 3] * xs[2 * j + 3];
        z[o * 20 + j] = fmaxf(v, 0.f);
    }
    __syncthreads();

    for (int idx = tid; idx < FEAT; idx += 128) {
        int o = idx / 19, j = idx % 19;
        g_feat[(size_t)s * FEAT + idx] = fmaxf(z[o * 20 + j], z[o * 20 + j + 1]);
    }
}

// conv2(k=2, 2->32ch) + relu + maxpool3 -> y (512, 9504)
__global__ void conv2pool_kernel(const float* __restrict__ w2,
                                 const float* __restrict__ b2)
{
    const int n = blockIdx.y;
    const int k = blockIdx.x * blockDim.x + threadIdx.x;
    if (k >= YK) return;
    const int o = k / 297, jj = k % 297;
    const float* lo = g_both + (size_t)n * HF;
    const float* ro = g_both + (size_t)(NB + n) * HF;
    const float w00 = w2[o * 4 + 0], w01 = w2[o * 4 + 1];
    const float w10 = w2[o * 4 + 2], w11 = w2[o * 4 + 3];
    const float bb = b2[o];
    float l0 = lo[jj], l1 = lo[jj + 1], l2v = lo[jj + 2], l3 = lo[jj + 3];
    float r0 = ro[jj], r1 = ro[jj + 1], r2v = ro[jj + 2], r3 = ro[jj + 3];
    float z0 = bb + w00 * l0 + w01 * l1  + w10 * r0 + w11 * r1;
    float z1 = bb + w00 * l1 + w01 * l2v + w10 * r1 + w11 * r2v;
    float z2 = bb + w00 * l2v + w01 * l3 + w10 * r2v + w11 * r3;
    float v = fmaxf(fmaxf(z0, z1), fmaxf(z2, 0.f));
    g_y[(size_t)n * YK + k] = v;
}

// out = relu((i2h + hidden) @ out_w^T + out_b) -> (512,10)
__global__ void out_kernel(const float* __restrict__ i2h,
                           const float* __restrict__ hid,
                           const float* __restrict__ ow,
                           const float* __restrict__ ob,
                           float* __restrict__ out)
{
    const int n    = blockIdx.x;
    const int m    = threadIdx.x >> 5;
    const int lane = threadIdx.x & 31;
    const float* a = i2h + (size_t)n * HID;
    const float* h = hid + (size_t)n * HID;
    const float* w = ow + (size_t)m * HID;
    float s = 0.f;
    for (int k = lane; k < HID; k += 32) s += (a[k] + h[k]) * w[k];
    #pragma unroll
    for (int o = 16; o; o >>= 1) s += __shfl_down_sync(0xffffffffu, s, o);
    if (lane == 0) out[n * OUT + m] = fmaxf(s + ob[m], 0.f);
}

// ---------------------------------------------------------------------------
extern "C" void kernel_launch(void* const* d_in, const int* in_sizes, int n_in,
                              void* d_out, int out_size)
{
    const float* hand_data = (const float*)d_in[0];
    const float* hidden    = (const float*)d_in[1];
    const float* l_conv_w  = (const float*)d_in[2];
    const float* l_conv_b  = (const float*)d_in[3];
    const float* l_fc_w    = (const float*)d_in[4];
    const float* l_fc_b    = (const float*)d_in[5];
    const float* r_conv_w  = (const float*)d_in[6];
    const float* r_conv_b  = (const float*)d_in[7];
    const float* r_fc_w    = (const float*)d_in[8];
    const float* r_fc_b    = (const float*)d_in[9];
    const float* conv2_w   = (const float*)d_in[10];
    const float* conv2_b   = (const float*)d_in[11];
    const float* l2_w      = (const float*)d_in[12];
    const float* l2_b      = (const float*)d_in[13];
    const float* h2h_w     = (const float*)d_in[14];
    const float* h2h_b     = (const float*)d_in[15];
    const float* out_w     = (const float*)d_in[16];
    const float* out_b     = (const float*)d_in[17];

    const int T    = in_sizes[0] / (NB * 84);
    const int tOff = (T - 1) * NB * 84;

    float *feat, *both, *y, *i2h, *part, *Wpad, *h0pad, *M0, *M1, *cv0, *cv1, *hid;
    cudaGetSymbolAddress((void**)&feat,  g_feat);
    cudaGetSymbolAddress((void**)&both,  g_both);
    cudaGetSymbolAddress((void**)&y,     g_y);
    cudaGetSymbolAddress((void**)&i2h,   g_i2h);
    cudaGetSymbolAddress((void**)&part,  g_part);
    cudaGetSymbolAddress((void**)&Wpad,  g_Wpad);
    cudaGetSymbolAddress((void**)&h0pad, g_h0pad);
    cudaGetSymbolAddress((void**)&M0,    g_M0);
    cudaGetSymbolAddress((void**)&M1,    g_M1);
    cudaGetSymbolAddress((void**)&cv0,   g_cv0);
    cudaGetSymbolAddress((void**)&cv1,   g_cv1);
    cudaGetSymbolAddress((void**)&hid,   g_hid);

    // 1) pad W / h0, init c0
    pad_kernel<<<(HIDP * HIDP + 255) / 256, 256>>>(h2h_w, h2h_b, hidden);

    // 2) hand features (last frame only)
    hand_feat_kernel<<<1024, 128>>>(hand_data, l_conv_w, l_conv_b, r_conv_w, r_conv_b, tOff);

    // 3) per-hand fc GEMMs (relu)
    gemm_kernel<true, true, false><<<dim3((HF + BN - 1) / BN, NB / BM), 256>>>(
        NB, HF, FEAT, feat, FEAT, l_fc_w, FEAT, l_fc_b, both, HF, 0);
    gemm_kernel<true, true, false><<<dim3((HF + BN - 1) / BN, NB / BM), 256>>>(
        NB, HF, FEAT, feat + (size_t)NB * FEAT, FEAT, r_fc_w, FEAT, r_fc_b,
        both + (size_t)NB * HF, HF, 0);

    // 4) conv2 + relu + maxpool3 -> y
    conv2pool_kernel<<<dim3((YK + 255) / 256, NB), 256>>>(conv2_w, conv2_b);

    // 5) l2 GEMM (split-K = 4) + reduce with bias
    gemm_kernel<true, false, true><<<dim3((HID + BN - 1) / BN, NB / BM, 4), 256>>>(
        NB, HID, YK, y, YK, l2_w, YK, nullptr, part, HID, 2384);
    splitk_reduce<<<(NB * HID + 255) / 256, 256>>>(part, l2_b, i2h, NB, HID, 4);

    // 6) affine doubling: (W, b) -> (W^32, c32); 5 iterations on padded bufs
    float* Mbuf[2] = { M0, M1 };
    float* cbuf[2] = { cv0, cv1 };
    for (int i = 0; i < 5; ++i) {
        const float* srcM = (i == 0) ? Wpad : Mbuf[1 - (i & 1)];
        float* dstM = Mbuf[i & 1];
        const float* srcC = cbuf[i & 1];
        float* dstC = cbuf[1 - (i & 1)];
        gemm_kernel<false, false, false><<<dim3(HIDP / BN, HIDP / BM), 256>>>(
            HIDP, HIDP, HIDP, srcM, HIDP, srcM, HIDP, nullptr, dstM, HIDP, 0);
        vec_affine<<<128, 128>>>(srcC, srcM, dstC);
    }
    // final: M32 in Mbuf[0] (i=4 -> dst Mbuf[0]); c32 in cbuf[1] (i=4 src cv0 -> dst cv1)

    // 7) hidden_final = h0 @ M32^T + c32
    float* hidC = (out_size >= NB * OUT + NB * HID) ? ((float*)d_out) + NB * OUT : hid;
    gemm_kernel<true, false, false><<<dim3((HID + BN - 1) / BN, NB / BM), 256>>>(
        NB, HID, HIDP, h0pad, HIDP, M0, HIDP, cv1, hidC, HID, 0);

    // 8) out = relu((i2h + hidden_final) @ out_w^T + out_b)
    out_kernel<<<NB, OUT * 32>>>(i2h, hidC, out_w, out_b, (float*)d_out);
}

// round 2
// speedup vs baseline: 1.3807x; 1.3807x over previous
#include <cuda_runtime.h>
#include <cuda_bf16.h>

// ---------------------------------------------------------------------------
// ASLRNN3: only the last frame feeds outs[-1]; hidden recurrence is affine and
// independent of i2h. All big GEMMs run on tensor cores via bf16-split 3-MMA
// (hi*hi + hi*lo + lo*hi), ~1.5e-5 elementwise accuracy, fp32 accumulate.
// ---------------------------------------------------------------------------

#define NB 512
#define FEAT 304
#define HF 300
#define YK 9504
#define HID 500
#define HIDP 512
#define OUT 10

// ---- scratch (device globals) ----
__device__ float g_feat[1024 * FEAT];
__device__ float g_both[1024 * HF];
__device__ float g_y[NB * YK];
__device__ float g_i2h[NB * HID];
__device__ float g_part[4 * NB * HID];
__device__ float g_Wpad[HIDP * HIDP];
__device__ float g_h0pad[NB * HIDP];
__device__ float g_M0[HIDP * HIDP];
__device__ float g_M1[HIDP * HIDP];
__device__ float g_cv0[HIDP];
__device__ float g_cv1[HIDP];
__device__ float g_hid[NB * HID];

// ---------------------------------------------------------------------------
// Tensor-core GEMM: C(M,N) = A(M,K) * op(B) [+bias] [relu]
//  TRANSB=true : B is (N,K) row-major  (A @ B^T)
//  TRANSB=false: B is (K,N) row-major  (A @ B)
//  SPLIT=true  : gridDim.z split-K partials (no bias/relu)
//  DUAL=true   : blocks with blockIdx.y >= gridDim.y/2 use B2/bias2
// Requirements: M % 64 == 0, K % 16 == 0 (per split chunk), lda/ldb % 4 == 0.
// ---------------------------------------------------------------------------
#define SA 24   // smem row stride in bf16 elems (48B) -> conflict-free frags

#define MMA16816(c, a, b) asm volatile( \
    "mma.sync.aligned.m16n8k16.row.col.f32.bf16.bf16.f32 " \
    "{%0,%1,%2,%3},{%4,%5,%6,%7},{%8,%9},{%0,%1,%2,%3};\n" \
    : "+f"((c)[0]), "+f"((c)[1]), "+f"((c)[2]), "+f"((c)[3]) \
    : "r"((a)[0]), "r"((a)[1]), "r"((a)[2]), "r"((a)[3]), \
      "r"((b)[0]), "r"((b)[1]))

__device__ __forceinline__ unsigned ld32bf(const __nv_bfloat16* p) {
    return *reinterpret_cast<const unsigned*>(p);
}

__device__ __forceinline__ void split_store(__nv_bfloat16* hi, __nv_bfloat16* lo,
                                            int idx, float x) {
    __nv_bfloat16 h = __float2bfloat16(x);
    hi[idx] = h;
    lo[idx] = __float2bfloat16(x - __bfloat162float(h));
}

template<bool TRANSB, bool RELU, bool SPLIT, bool DUAL>
__global__ __launch_bounds__(256)
void mma_gemm(int M, int N, int K,
              const float* __restrict__ A, int lda,
              const float* __restrict__ B, int ldb,
              const float* __restrict__ bias,
              float* __restrict__ C, int ldc, int splitLen,
              const float* __restrict__ B2, const float* __restrict__ bias2)
{
    __shared__ __nv_bfloat16 sm[4 * 64 * SA];
    __nv_bfloat16* Ah = sm;
    __nv_bfloat16* Al = sm + 64 * SA;
    __nv_bfloat16* Bh = sm + 2 * 64 * SA;
    __nv_bfloat16* Bl = sm + 3 * 64 * SA;

    const int tid  = threadIdx.x;
    const int wid  = tid >> 5;
    const int lane = tid & 31;
    const int wm   = (wid >> 2) * 32;   // warp m offset (0 or 32)
    const int wn   = (wid & 3) * 16;    // warp n offset (0,16,32,48)
    const int lr   = lane >> 2;         // 0..7
    const int lc   = lane & 3;          // 0..3
    const int m0   = blockIdx.y * 64;
    const int n0   = blockIdx.x * 64;

    if (DUAL && blockIdx.y >= (gridDim.y >> 1)) { B = B2; bias = bias2; }

    int kbeg = 0, kend = K;
    if (SPLIT) {
        kbeg = blockIdx.z * splitLen;
        kend = min(K, kbeg + splitLen);
        C += (size_t)blockIdx.z * (size_t)M * (size_t)ldc;
    }

    float acc[2][2][4] = {};

    const int sr  = tid >> 2;           // 0..63
    const int sc  = (tid & 3) * 4;      // 0,4,8,12
    const int bkr = tid >> 4;           // 0..15 (nontrans B k row)
    const int bn4 = (tid & 15) * 4;     // 0..60

    for (int k0 = kbeg; k0 < kend; k0 += 16) {
        // ---- stage A tile as [m][k] (k contiguous)
        {
            const float4 v = *reinterpret_cast<const float4*>(
                &A[(size_t)(m0 + sr) * lda + k0 + sc]);
            split_store(Ah, Al, sr * SA + sc + 0, v.x);
            split_store(Ah, Al, sr * SA + sc + 1, v.y);
            split_store(Ah, Al, sr * SA + sc + 2, v.z);
            split_store(Ah, Al, sr * SA + sc + 3, v.w);
        }
        // ---- stage B tile as [n][k] (k contiguous)
        if (TRANSB) {
            float4 v = make_float4(0.f, 0.f, 0.f, 0.f);
            if (n0 + sr < N)
                v = *reinterpret_cast<const float4*>(
                    &B[(size_t)(n0 + sr) * ldb + k0 + sc]);
            split_store(Bh, Bl, sr * SA + sc + 0, v.x);
            split_store(Bh, Bl, sr * SA + sc + 1, v.y);
            split_store(Bh, Bl, sr * SA + sc + 2, v.z);
            split_store(Bh, Bl, sr * SA + sc + 3, v.w);
        } else {
            const float* bp = &B[(size_t)(k0 + bkr) * ldb + n0 + bn4];
            float4 v;
            if (n0 + bn4 + 3 < N) {
                v = *reinterpret_cast<const float4*>(bp);
            } else {
                v.x = (n0 + bn4 + 0 < N) ? bp[0] : 0.f;
                v.y = (n0 + bn4 + 1 < N) ? bp[1] : 0.f;
                v.z = (n0 + bn4 + 2 < N) ? bp[2] : 0.f;
                v.w = (n0 + bn4 + 3 < N) ? bp[3] : 0.f;
            }
            split_store(Bh, Bl, (bn4 + 0) * SA + bkr, v.x);
            split_store(Bh, Bl, (bn4 + 1) * SA + bkr, v.y);
            split_store(Bh, Bl, (bn4 + 2) * SA + bkr, v.z);
            split_store(Bh, Bl, (bn4 + 3) * SA + bkr, v.w);
        }
        __syncthreads();

        // ---- fragments
        unsigned a_h[2][4], a_l[2][4], b_h[2][2], b_l[2][2];
        #pragma unroll
        for (int mt = 0; mt < 2; ++mt) {
            const __nv_bfloat16* p = Ah + (wm + mt * 16 + lr) * SA + lc * 2;
            const __nv_bfloat16* q = Al + (wm + mt * 16 + lr) * SA + lc * 2;
            a_h[mt][0] = ld32bf(p);
            a_h[mt][1] = ld32bf(p + 8 * SA);
            a_h[mt][2] = ld32bf(p + 8);
            a_h[mt][3] = ld32bf(p + 8 * SA + 8);
            a_l[mt][0] = ld32bf(q);
            a_l[mt][1] = ld32bf(q + 8 * SA);
            a_l[mt][2] = ld32bf(q + 8);
            a_l[mt][3] = ld32bf(q + 8 * SA + 8);
        }
        #pragma unroll
        for (int nt = 0; nt < 2; ++nt) {
            const __nv_bfloat16* p = Bh + (wn + nt * 8 + lr) * SA + lc * 2;
            const __nv_bfloat16* q = Bl + (wn + nt * 8 + lr) * SA + lc * 2;
            b_h[nt][0] = ld32bf(p);
            b_h[nt][1] = ld32bf(p + 8);
            b_l[nt][0] = ld32bf(q);
            b_l[nt][1] = ld32bf(q + 8);
        }
        #pragma unroll
        for (int mt = 0; mt < 2; ++mt)
            #pragma unroll
            for (int nt = 0; nt < 2; ++nt) {
                MMA16816(acc[mt][nt], a_h[mt], b_h[nt]);
                MMA16816(acc[mt][nt], a_h[mt], b_l[nt]);
                MMA16816(acc[mt][nt], a_l[mt], b_h[nt]);
            }
        __syncthreads();
    }

    // ---- epilogue
    #pragma unroll
    for (int mt = 0; mt < 2; ++mt) {
        #pragma unroll
        for (int nt = 0; nt < 2; ++nt) {
            const int row = m0 + wm + mt * 16 + lr;
            const int col = n0 + wn + nt * 8 + lc * 2;
            float* Cp0 = C + (size_t)row * ldc;
            float* Cp1 = C + (size_t)(row + 8) * ldc;
            #pragma unroll
            for (int j = 0; j < 2; ++j) {
                if (col + j < N) {
                    float v0 = acc[mt][nt][j];
                    float v1 = acc[mt][nt][2 + j];
                    if (!SPLIT) {
                        if (bias) { v0 += bias[col + j]; v1 += bias[col + j]; }
                        if (RELU) { v0 = fmaxf(v0, 0.f); v1 = fmaxf(v1, 0.f); }
                    }
                    Cp0[col + j] = v0;
                    Cp1[col + j] = v1;
                }
            }
        }
    }
}

// ---------------------------------------------------------------------------
__global__ void splitk_reduce(const float* __restrict__ part,
                              const float* __restrict__ bias,
                              float* __restrict__ C, int M, int N, int S)
{
    int idx = blockIdx.x * blockDim.x + threadIdx.x;
    if (idx >= M * N) return;
    int n = idx % N;
    float v = bias ? bias[n] : 0.f;
    for (int s = 0; s < S; ++s) v += part[(size_t)s * M * N + idx];
    C[idx] = v;
}

// Pad W -> (512,512), h0 -> (512,512 cols), init c0 = padded bias
__global__ void pad_kernel(const float* __restrict__ W,
                           const float* __restrict__ b,
                           const float* __restrict__ h0)
{
    int idx = blockIdx.x * blockDim.x + threadIdx.x;
    if (idx >= HIDP * HIDP) return;
    int r = idx >> 9, c = idx & (HIDP - 1);
    g_Wpad[idx]  = (r < HID && c < HID) ? W[r * HID + c] : 0.f;
    g_h0pad[idx] = (c < HID) ? h0[r * HID + c] : 0.f;
    if (idx < HIDP) g_cv0[idx] = (idx < HID) ? b[idx] : 0.f;
}

// c_new[j] = c[j] + sum_i c[i] * M[j][i]
__global__ void vec_affine(const float* __restrict__ c,
                           const float* __restrict__ Mm,
                           float* __restrict__ cnew)
{
    int wid  = (blockIdx.x * blockDim.x + threadIdx.x) >> 5;
    int lane = threadIdx.x & 31;
    if (wid >= HIDP) return;
    float s = 0.f;
    for (int i = lane; i < HIDP; i += 32) s += c[i] * Mm[wid * HIDP + i];
    #pragma unroll
    for (int o = 16; o; o >>= 1) s += __shfl_down_sync(0xffffffffu, s, o);
    if (lane == 0) cnew[wid] = c[wid] + s;
}

// hand branch: conv1d(k=2, 2->16ch) + relu + maxpool2 -> feat (304 per sample)
__global__ void hand_feat_kernel(const float* __restrict__ hd,
                                 const float* __restrict__ lcw, const float* __restrict__ lcb,
                                 const float* __restrict__ rcw, const float* __restrict__ rcb,
                                 int tOff)
{
    const int s    = blockIdx.x;      // 0..1023
    const int n    = s & (NB - 1);
    const int hand = s >> 9;
    const float* x  = hd + tOff + n * 84 + hand * 42;
    const float* cw = hand ? rcw : lcw;
    const float* cb = hand ? rcb : lcb;

    __shared__ float xs[42];
    __shared__ float z[16 * 20];
    const int tid = threadIdx.x;
    if (tid < 42) xs[tid] = x[tid];
    __syncthreads();

    for (int idx = tid; idx < 320; idx += 128) {
        int o = idx / 20, j = idx % 20;
        float v = cb[o]
                + cw[o * 4 + 0] * xs[2 * j]
                + cw[o * 4 + 1] * xs[2 * j + 2]
                + cw[o * 4 + 2] * xs[2 * j + 1]
                + cw[o * 4 + 3] * xs[2 * j + 3];
        z[o * 20 + j] = fmaxf(v, 0.f);
    }
    __syncthreads();

    for (int idx = tid; idx < FEAT; idx += 128) {
        int o = idx / 19, j = idx % 19;
        g_feat[(size_t)s * FEAT + idx] = fmaxf(z[o * 20 + j], z[o * 20 + j + 1]);
    }
}

// conv2(k=2, 2->32ch) + relu + maxpool3 -> y (512, 9504)
__global__ void conv2pool_kernel(const float* __restrict__ w2,
                                 const float* __restrict__ b2)
{
    const int n = blockIdx.y;
    const int k = blockIdx.x * blockDim.x + threadIdx.x;
    if (k >= YK) return;
    const int o = k / 297, jj = k % 297;
    const float* lo = g_both + (size_t)n * HF;
    const float* ro = g_both + (size_t)(NB + n) * HF;
    const float w00 = w2[o * 4 + 0], w01 = w2[o * 4 + 1];
    const float w10 = w2[o * 4 + 2], w11 = w2[o * 4 + 3];
    const float bb = b2[o];
    float l0 = lo[jj], l1 = lo[jj + 1], l2v = lo[jj + 2], l3 = lo[jj + 3];
    float r0 = ro[jj], r1 = ro[jj + 1], r2v = ro[jj + 2], r3 = ro[jj + 3];
    float z0 = bb + w00 * l0 + w01 * l1  + w10 * r0 + w11 * r1;
    float z1 = bb + w00 * l1 + w01 * l2v + w10 * r1 + w11 * r2v;
    float z2 = bb + w00 * l2v + w01 * l3 + w10 * r2v + w11 * r3;
    float v = fmaxf(fmaxf(z0, z1), fmaxf(z2, 0.f));
    g_y[(size_t)n * YK + k] = v;
}

// out = relu((i2h + hidden) @ out_w^T + out_b) -> (512,10)
__global__ void out_kernel(const float* __restrict__ i2h,
                           const float* __restrict__ hid,
                           const float* __restrict__ ow,
                           const float* __restrict__ ob,
                           float* __restrict__ out)
{
    const int n    = blockIdx.x;
    const int m    = threadIdx.x >> 5;
    const int lane = threadIdx.x & 31;
    const float* a = i2h + (size_t)n * HID;
    const float* h = hid + (size_t)n * HID;
    const float* w = ow + (size_t)m * HID;
    float s = 0.f;
    for (int k = lane; k < HID; k += 32) s += (a[k] + h[k]) * w[k];
    #pragma unroll
    for (int o = 16; o; o >>= 1) s += __shfl_down_sync(0xffffffffu, s, o);
    if (lane == 0) out[n * OUT + m] = fmaxf(s + ob[m], 0.f);
}

// ---------------------------------------------------------------------------
extern "C" void kernel_launch(void* const* d_in, const int* in_sizes, int n_in,
                              void* d_out, int out_size)
{
    const float* hand_data = (const float*)d_in[0];
    const float* hidden    = (const float*)d_in[1];
    const float* l_conv_w  = (const float*)d_in[2];
    const float* l_conv_b  = (const float*)d_in[3];
    const float* l_fc_w    = (const float*)d_in[4];
    const float* l_fc_b    = (const float*)d_in[5];
    const float* r_conv_w  = (const float*)d_in[6];
    const float* r_conv_b  = (const float*)d_in[7];
    const float* r_fc_w    = (const float*)d_in[8];
    const float* r_fc_b    = (const float*)d_in[9];
    const float* conv2_w   = (const float*)d_in[10];
    const float* conv2_b   = (const float*)d_in[11];
    const float* l2_w      = (const float*)d_in[12];
    const float* l2_b      = (const float*)d_in[13];
    const float* h2h_w     = (const float*)d_in[14];
    const float* h2h_b     = (const float*)d_in[15];
    const float* out_w     = (const float*)d_in[16];
    const float* out_b     = (const float*)d_in[17];

    const int T    = in_sizes[0] / (NB * 84);
    const int tOff = (T - 1) * NB * 84;

    float *feat, *both, *y, *i2h, *part, *Wpad, *h0pad, *M0, *M1, *cv0, *cv1, *hid;
    cudaGetSymbolAddress((void**)&feat,  g_feat);
    cudaGetSymbolAddress((void**)&both,  g_both);
    cudaGetSymbolAddress((void**)&y,     g_y);
    cudaGetSymbolAddress((void**)&i2h,   g_i2h);
    cudaGetSymbolAddress((void**)&part,  g_part);
    cudaGetSymbolAddress((void**)&Wpad,  g_Wpad);
    cudaGetSymbolAddress((void**)&h0pad, g_h0pad);
    cudaGetSymbolAddress((void**)&M0,    g_M0);
    cudaGetSymbolAddress((void**)&M1,    g_M1);
    cudaGetSymbolAddress((void**)&cv0,   g_cv0);
    cudaGetSymbolAddress((void**)&cv1,   g_cv1);
    cudaGetSymbolAddress((void**)&hid,   g_hid);

    // 1) pad W / h0, init c0
    pad_kernel<<<(HIDP * HIDP + 255) / 256, 256>>>(h2h_w, h2h_b, hidden);

    // 2) hand features (last frame only)
    hand_feat_kernel<<<1024, 128>>>(hand_data, l_conv_w, l_conv_b, r_conv_w, r_conv_b, tOff);

    // 3) both fc GEMMs in one dual launch: rows 0-511 left, 512-1023 right
    mma_gemm<true, true, false, true><<<dim3(5, 16), 256>>>(
        1024, HF, FEAT, feat, FEAT, l_fc_w, FEAT, l_fc_b, both, HF, 0,
        r_fc_w, r_fc_b);

    // 4) conv2 + relu + maxpool3 -> y
    conv2pool_kernel<<<dim3((YK + 255) / 256, NB), 256>>>(conv2_w, conv2_b);

    // 5) l2 GEMM (split-K = 4) + reduce with bias
    mma_gemm<true, false, true, false><<<dim3(8, 8, 4), 256>>>(
        NB, HID, YK, y, YK, l2_w, YK, nullptr, part, HID, 2384, nullptr, nullptr);
    splitk_reduce<<<(NB * HID + 255) / 256, 256>>>(part, l2_b, i2h, NB, HID, 4);

    // 6) affine doubling: (W, b) -> (W^32, c32); 5 iterations on padded bufs
    float* Mbuf[2] = { M0, M1 };
    float* cbuf[2] = { cv0, cv1 };
    for (int i = 0; i < 5; ++i) {
        const float* srcM = (i == 0) ? Wpad : Mbuf[1 - (i & 1)];
        float* dstM = Mbuf[i & 1];
        const float* srcC = cbuf[i & 1];
        float* dstC = cbuf[1 - (i & 1)];
        mma_gemm<false, false, false, false><<<dim3(8, 8), 256>>>(
            HIDP, HIDP, HIDP, srcM, HIDP, srcM, HIDP, nullptr, dstM, HIDP, 0,
            nullptr, nullptr);
        vec_affine<<<128, 128>>>(srcC, srcM, dstC);
    }
    // M32 in M0; c32 in cv1

    // 7) hidden_final = h0 @ M32^T + c32 -> into d_out tail
    float* hidC = (out_size >= NB * OUT + NB * HID) ? ((float*)d_out) + NB * OUT : hid;
    mma_gemm<true, false, false, false><<<dim3(8, 8), 256>>>(
        NB, HID, HIDP, h0pad, HIDP, M0, HIDP, cv1, hidC, HID, 0,
        nullptr, nullptr);

    // 8) out = relu((i2h + hidden_final) @ out_w^T + out_b)
    out_kernel<<<NB, OUT * 32>>>(i2h, hidC, out_w, out_b, (float*)d_out);
}

// round 3
// speedup vs baseline: 1.5770x; 1.1422x over previous
#include <cuda_runtime.h>
#include <cuda_bf16.h>

// ---------------------------------------------------------------------------
// ASLRNN3 sm_100a. Facts used:
//  * only last frame feeds outs[-1]
//  * hidden recurrence is affine & independent of i2h -> homogeneous 501x501
//    matrix power by 5 squarings (embedded in 512x512 pad)
//  * all GEMMs on tensor cores via bf16 hi/lo split 3-MMA (fp32 accum)
//  * all GEMM A operands pre-split to bf16 pairs; chain epilogue re-splits
// ---------------------------------------------------------------------------

#define NB 512
#define FEAT 304
#define HF 300
#define YK 9504
#define HID 500
#define HIDP 512
#define OUT 10
#define SPLITK 3
#define SPLITLEN 3168   // 99 * 32, 3*3168 = 9504

// ---- scratch ----
__device__ __nv_bfloat16 g_feath[1024 * FEAT];
__device__ __nv_bfloat16 g_featl[1024 * FEAT];
__device__ float         g_both [1024 * HF];
__device__ __nv_bfloat16 g_yh[NB * YK];
__device__ __nv_bfloat16 g_yl[NB * YK];
__device__ float         g_part[SPLITK * NB * HID];
__device__ __nv_bfloat16 g_Wh [HIDP * HIDP];
__device__ __nv_bfloat16 g_Wl [HIDP * HIDP];
__device__ __nv_bfloat16 g_M0h[HIDP * HIDP];
__device__ __nv_bfloat16 g_M0l[HIDP * HIDP];
__device__ __nv_bfloat16 g_M1h[HIDP * HIDP];
__device__ __nv_bfloat16 g_M1l[HIDP * HIDP];
__device__ __nv_bfloat16 g_h0h[NB * HIDP];
__device__ __nv_bfloat16 g_h0l[NB * HIDP];
__device__ float         g_hid[NB * HID];

#define MMA16816(c, a, b) asm volatile( \
    "mma.sync.aligned.m16n8k16.row.col.f32.bf16.bf16.f32 " \
    "{%0,%1,%2,%3},{%4,%5,%6,%7},{%8,%9},{%0,%1,%2,%3};\n" \
    : "+f"((c)[0]), "+f"((c)[1]), "+f"((c)[2]), "+f"((c)[3]) \
    : "r"((a)[0]), "r"((a)[1]), "r"((a)[2]), "r"((a)[3]), \
      "r"((b)[0]), "r"((b)[1]))

__device__ __forceinline__ unsigned ld32bf(const __nv_bfloat16* p) {
    return *reinterpret_cast<const unsigned*>(p);
}
__device__ __forceinline__ void split_pair(float x, __nv_bfloat16& h, __nv_bfloat16& l) {
    h = __float2bfloat16(x);
    l = __float2bfloat16(x - __bfloat162float(h));
}

// ---------------------------------------------------------------------------
// Tensor-core GEMM. A is ALWAYS a pre-split bf16 pair (Agh/Agl), row-major.
//  BPAIR : B is a pre-split pair (else fp32, split during staging)
//  TRANSB: B is (N,K) row-major (A@B^T); else (K,N) row-major (A@B)
//  SPLIT : gridDim.z split-K partials (no bias/relu)
//  DUAL  : blocks with blockIdx.y >= gridDim.y/2 use Bf2/bias2 (fp32 B only)
//  OUTPAIR: epilogue writes bf16 hi/lo pair (Cgh/Cgl) instead of fp32 C
// M%64==0, K%BK==0, ld*%8==0.
// ---------------------------------------------------------------------------
template<int BK, bool BPAIR, bool TRANSB, bool RELU, bool SPLIT, bool DUAL, bool OUTPAIR>
__global__ __launch_bounds__(256)
void mma_gemm(int M, int N, int K,
              const __nv_bfloat16* __restrict__ Agh,
              const __nv_bfloat16* __restrict__ Agl, int lda,
              const float* __restrict__ Bf,
              const __nv_bfloat16* __restrict__ Bgh,
              const __nv_bfloat16* __restrict__ Bgl, int ldb,
              const float* __restrict__ bias,
              float* __restrict__ C,
              __nv_bfloat16* __restrict__ Cgh,
              __nv_bfloat16* __restrict__ Cgl, int ldc,
              const float* __restrict__ Bf2, const float* __restrict__ bias2)
{
    constexpr int SA = BK + 8;
    __shared__ __nv_bfloat16 sm[4 * 64 * SA];
    __nv_bfloat16* Ah = sm;
    __nv_bfloat16* Al = sm + 64 * SA;
    __nv_bfloat16* Bh = sm + 2 * 64 * SA;
    __nv_bfloat16* Bl = sm + 3 * 64 * SA;

    const int tid  = threadIdx.x;
    const int wid  = tid >> 5;
    const int lane = tid & 31;
    const int wm   = (wid >> 2) * 32;
    const int wn   = (wid & 3) * 16;
    const int lr   = lane >> 2;
    const int lc   = lane & 3;
    const int m0   = blockIdx.y * 64;
    const int n0   = blockIdx.x * 64;

    if (DUAL && blockIdx.y >= (gridDim.y >> 1)) { Bf = Bf2; bias = bias2; }

    int kbeg = 0, kend = K;
    if (SPLIT) {
        kbeg = blockIdx.z * SPLITLEN;
        kend = min(K, kbeg + SPLITLEN);
        C += (size_t)blockIdx.z * (size_t)M * (size_t)ldc;
    }

    float acc[2][2][4] = {};

    // staging thread roles
    const int ar = tid >> 2;
    const int ac = (tid & 3) * (BK / 4);

    // prefetch registers
    uint4  rAh = {0,0,0,0}, rAl = {0,0,0,0};
    uint4  rBh = {0,0,0,0}, rBl = {0,0,0,0};
    float4 rB0 = {0,0,0,0}, rB1 = {0,0,0,0};

    auto loadT = [&](int k0) {
        // A pair
        {
            const size_t off = (size_t)(m0 + ar) * lda + k0 + ac;
            if (BK == 32) {
                rAh = *reinterpret_cast<const uint4*>(Agh + off);
                rAl = *reinterpret_cast<const uint4*>(Agl + off);
            } else {
                uint2 h = *reinterpret_cast<const uint2*>(Agh + off);
                uint2 l = *reinterpret_cast<const uint2*>(Agl + off);
                rAh.x = h.x; rAh.y = h.y; rAl.x = l.x; rAl.y = l.y;
            }
        }
        // B
        if (TRANSB) {
            if (BPAIR) {
                const size_t off = (size_t)(n0 + ar) * ldb + k0 + ac;
                if (n0 + ar < N) {
                    rBh = *reinterpret_cast<const uint4*>(Bgh + off);
                    rBl = *reinterpret_cast<const uint4*>(Bgl + off);
                } else { rBh = make_uint4(0,0,0,0); rBl = make_uint4(0,0,0,0); }
            } else {
                const size_t off = (size_t)(n0 + ar) * ldb + k0 + ac;
                if (n0 + ar < N) {
                    rB0 = *reinterpret_cast<const float4*>(Bf + off);
                    if (BK == 32) rB1 = *reinterpret_cast<const float4*>(Bf + off + 4);
                } else { rB0 = make_float4(0,0,0,0); rB1 = make_float4(0,0,0,0); }
            }
        } else {
            // pair only (chain): [k][n] -> load 8 bf16 of row k
            const int bkr = tid >> 3;
            const int bn8 = (tid & 7) * 8;
            const size_t off = (size_t)(k0 + bkr) * ldb + n0 + bn8;
            rBh = *reinterpret_cast<const uint4*>(Bgh + off);
            rBl = *reinterpret_cast<const uint4*>(Bgl + off);
        }
    };

    auto storeT = [&]() {
        // A
        if (BK == 32) {
            *reinterpret_cast<uint4*>(Ah + ar * SA + ac) = rAh;
            *reinterpret_cast<uint4*>(Al + ar * SA + ac) = rAl;
        } else {
            *reinterpret_cast<uint2*>(Ah + ar * SA + ac) = make_uint2(rAh.x, rAh.y);
            *reinterpret_cast<uint2*>(Al + ar * SA + ac) = make_uint2(rAl.x, rAl.y);
        }
        // B
        if (TRANSB) {
            if (BPAIR) {
                *reinterpret_cast<uint4*>(Bh + ar * SA + ac) = rBh;
                *reinterpret_cast<uint4*>(Bl + ar * SA + ac) = rBl;
            } else {
                const float* v0 = reinterpret_cast<const float*>(&rB0);
                #pragma unroll
                for (int e = 0; e < 4; ++e)
                    split_pair(v0[e], Bh[ar * SA + ac + e], Bl[ar * SA + ac + e]);
                if (BK == 32) {
                    const float* v1 = reinterpret_cast<const float*>(&rB1);
                    #pragma unroll
                    for (int e = 0; e < 4; ++e)
                        split_pair(v1[e], Bh[ar * SA + ac + 4 + e], Bl[ar * SA + ac + 4 + e]);
                }
            }
        } else {
            const int bkr = tid >> 3;
            const int bn8 = (tid & 7) * 8;
            const __nv_bfloat16* hv = reinterpret_cast<const __nv_bfloat16*>(&rBh);
            const __nv_bfloat16* lv = reinterpret_cast<const __nv_bfloat16*>(&rBl);
            #pragma unroll
            for (int e = 0; e < 8; ++e) {
                Bh[(bn8 + e) * SA + bkr] = hv[e];
                Bl[(bn8 + e) * SA + bkr] = lv[e];
            }
        }
    };

    loadT(kbeg);
    for (int k0 = kbeg; k0 < kend; k0 += BK) {
        storeT();
        __syncthreads();
        if (k0 + BK < kend) loadT(k0 + BK);

        #pragma unroll
        for (int s = 0; s < BK / 16; ++s) {
            const int kb = s * 16;
            unsigned a_h[2][4], a_l[2][4], b_h[2][2], b_l[2][2];
            #pragma unroll
            for (int mt = 0; mt < 2; ++mt) {
                const __nv_bfloat16* p = Ah + (wm + mt * 16 + lr) * SA + kb + lc * 2;
                const __nv_bfloat16* q = Al + (wm + mt * 16 + lr) * SA + kb + lc * 2;
                a_h[mt][0] = ld32bf(p);
                a_h[mt][1] = ld32bf(p + 8 * SA);
                a_h[mt][2] = ld32bf(p + 8);
                a_h[mt][3] = ld32bf(p + 8 * SA + 8);
                a_l[mt][0] = ld32bf(q);
                a_l[mt][1] = ld32bf(q + 8 * SA);
                a_l[mt][2] = ld32bf(q + 8);
                a_l[mt][3] = ld32bf(q + 8 * SA + 8);
            }
            #pragma unroll
            for (int nt = 0; nt < 2; ++nt) {
                const __nv_bfloat16* p = Bh + (wn + nt * 8 + lr) * SA + kb + lc * 2;
                const __nv_bfloat16* q = Bl + (wn + nt * 8 + lr) * SA + kb + lc * 2;
                b_h[nt][0] = ld32bf(p);
                b_h[nt][1] = ld32bf(p + 8);
                b_l[nt][0] = ld32bf(q);
                b_l[nt][1] = ld32bf(q + 8);
            }
            #pragma unroll
            for (int mt = 0; mt < 2; ++mt)
                #pragma unroll
                for (int nt = 0; nt < 2; ++nt) {
                    MMA16816(acc[mt][nt], a_h[mt], b_h[nt]);
                    MMA16816(acc[mt][nt], a_h[mt], b_l[nt]);
                    MMA16816(acc[mt][nt], a_l[mt], b_h[nt]);
                }
        }
        __syncthreads();
    }

    // epilogue
    #pragma unroll
    for (int mt = 0; mt < 2; ++mt) {
        #pragma unroll
        for (int nt = 0; nt < 2; ++nt) {
            const int row = m0 + wm + mt * 16 + lr;
            const int col = n0 + wn + nt * 8 + lc * 2;
            #pragma unroll
            for (int rr = 0; rr < 2; ++rr) {
                const int r = row + rr * 8;
                #pragma unroll
                for (int j = 0; j < 2; ++j) {
                    if (col + j < N) {
                        float v = acc[mt][nt][rr * 2 + j];
                        if (!SPLIT) {
                            if (bias) v += bias[col + j];
                            if (RELU) v = fmaxf(v, 0.f);
                        }
                        if (OUTPAIR) {
                            __nv_bfloat16 h, l;
                            split_pair(v, h, l);
                            Cgh[(size_t)r * ldc + col + j] = h;
                            Cgl[(size_t)r * ldc + col + j] = l;
                        } else {
                            C[(size_t)r * ldc + col + j] = v;
                        }
                    }
                }
            }
        }
    }
}

// ---------------------------------------------------------------------------
// Pad + homogeneous-augment: Waug (512^2 pair), h0aug (512^2 pair)
__global__ void pad_kernel(const float* __restrict__ W,
                           const float* __restrict__ b,
                           const float* __restrict__ h0)
{
    int idx = blockIdx.x * blockDim.x + threadIdx.x;
    if (idx >= HIDP * HIDP) return;
    int r = idx >> 9, c = idx & (HIDP - 1);
    float wv = 0.f;
    if (r < HID) {
        if (c < HID) wv = W[r * HID + c];
        else if (c == HID) wv = b[r];
    } else if (r == HID && c == HID) wv = 1.f;
    split_pair(wv, g_Wh[idx], g_Wl[idx]);
    float hv = (c < HID) ? h0[r * HID + c] : (c == HID ? 1.f : 0.f);
    split_pair(hv, g_h0h[idx], g_h0l[idx]);
}

// hand branch: conv1d(k=2,2->16) + relu + pool2 -> feat pair (1024 x 304)
__global__ void hand_feat_kernel(const float* __restrict__ hd,
                                 const float* __restrict__ lcw, const float* __restrict__ lcb,
                                 const float* __restrict__ rcw, const float* __restrict__ rcb,
                                 int tOff)
{
    const int s    = blockIdx.x;
    const int n    = s & (NB - 1);
    const int hand = s >> 9;
    const float* x  = hd + tOff + n * 84 + hand * 42;
    const float* cw = hand ? rcw : lcw;
    const float* cb = hand ? rcb : lcb;

    __shared__ float xs[42];
    __shared__ float z[16 * 20];
    const int tid = threadIdx.x;
    if (tid < 42) xs[tid] = x[tid];
    __syncthreads();

    for (int idx = tid; idx < 320; idx += 128) {
        int o = idx / 20, j = idx % 20;
        float v = cb[o]
                + cw[o * 4 + 0] * xs[2 * j]
                + cw[o * 4 + 1] * xs[2 * j + 2]
                + cw[o * 4 + 2] * xs[2 * j + 1]
                + cw[o * 4 + 3] * xs[2 * j + 3];
        z[o * 20 + j] = fmaxf(v, 0.f);
    }
    __syncthreads();

    for (int idx = tid; idx < FEAT; idx += 128) {
        int o = idx / 19, j = idx % 19;
        float v = fmaxf(z[o * 20 + j], z[o * 20 + j + 1]);
        split_pair(v, g_feath[(size_t)s * FEAT + idx], g_featl[(size_t)s * FEAT + idx]);
    }
}

// conv2(k=2,2->32) + relu + pool3 -> y pair (512 x 9504); one block per sample
__global__ __launch_bounds__(256)
void conv2pool_kernel(const float* __restrict__ w2, const float* __restrict__ b2)
{
    __shared__ float slo[HF], sro[HF], sw[128], sb[32];
    const int n = blockIdx.x;
    const int tid = threadIdx.x;
    for (int i = tid; i < HF; i += 256) {
        slo[i] = g_both[(size_t)n * HF + i];
        sro[i] = g_both[(size_t)(NB + n) * HF + i];
    }
    if (tid < 128) sw[tid] = w2[tid];
    if (tid < 32)  sb[tid] = b2[tid];
    __syncthreads();

    for (int k = tid; k < YK; k += 256) {
        const int o = k / 297, jj = k % 297;
        const float w00 = sw[o * 4 + 0], w01 = sw[o * 4 + 1];
        const float w10 = sw[o * 4 + 2], w11 = sw[o * 4 + 3];
        const float bb = sb[o];
        float l0 = slo[jj], l1 = slo[jj + 1], l2v = slo[jj + 2], l3 = slo[jj + 3];
        float r0 = sro[jj], r1 = sro[jj + 1], r2v = sro[jj + 2], r3 = sro[jj + 3];
        float z0 = bb + w00 * l0  + w01 * l1  + w10 * r0  + w11 * r1;
        float z1 = bb + w00 * l1  + w01 * l2v + w10 * r1  + w11 * r2v;
        float z2 = bb + w00 * l2v + w01 * l3  + w10 * r2v + w11 * r3;
        float v = fmaxf(fmaxf(z0, z1), fmaxf(z2, 0.f));
        split_pair(v, g_yh[(size_t)n * YK + k], g_yl[(size_t)n * YK + k]);
    }
}

// out = relu((part0+part1+part2+l2_b + hidden) @ out_w^T + out_b)
__global__ void out_kernel(const float* __restrict__ part,
                           const float* __restrict__ l2b,
                           const float* __restrict__ hid,
                           const float* __restrict__ ow,
                           const float* __restrict__ ob,
                           float* __restrict__ out)
{
    const int n    = blockIdx.x;
    const int m    = threadIdx.x >> 5;
    const int lane = threadIdx.x & 31;
    const float* p0 = part + (size_t)n * HID;
    const float* p1 = p0 + (size_t)NB * HID;
    const float* p2 = p1 + (size_t)NB * HID;
    const float* h  = hid + (size_t)n * HID;
    const float* w  = ow + (size_t)m * HID;
    float s = 0.f;
    for (int k = lane; k < HID; k += 32)
        s += (p0[k] + p1[k] + p2[k] + l2b[k] + h[k]) * w[k];
    #pragma unroll
    for (int o = 16; o; o >>= 1) s += __shfl_down_sync(0xffffffffu, s, o);
    if (lane == 0) out[n * OUT + m] = fmaxf(s + ob[m], 0.f);
}

// ---------------------------------------------------------------------------
extern "C" void kernel_launch(void* const* d_in, const int* in_sizes, int n_in,
                              void* d_out, int out_size)
{
    const float* hand_data = (const float*)d_in[0];
    const float* hidden    = (const float*)d_in[1];
    const float* l_conv_w  = (const float*)d_in[2];
    const float* l_conv_b  = (const float*)d_in[3];
    const float* l_fc_w    = (const float*)d_in[4];
    const float* l_fc_b    = (const float*)d_in[5];
    const float* r_conv_w  = (const float*)d_in[6];
    const float* r_conv_b  = (const float*)d_in[7];
    const float* r_fc_w    = (const float*)d_in[8];
    const float* r_fc_b    = (const float*)d_in[9];
    const float* conv2_w   = (const float*)d_in[10];
    const float* conv2_b   = (const float*)d_in[11];
    const float* l2_w      = (const float*)d_in[12];
    const float* l2_b      = (const float*)d_in[13];
    const float* h2h_w     = (const float*)d_in[14];
    const float* h2h_b     = (const float*)d_in[15];
    const float* out_w     = (const float*)d_in[16];
    const float* out_b     = (const float*)d_in[17];

    const int T    = in_sizes[0] / (NB * 84);
    const int tOff = (T - 1) * NB * 84;

    __nv_bfloat16 *feath, *featl, *yh, *yl, *Wh, *Wl, *M0h, *M0l, *M1h, *M1l, *h0h, *h0l;
    float *both, *part, *hid;
    cudaGetSymbolAddress((void**)&feath, g_feath);
    cudaGetSymbolAddress((void**)&featl, g_featl);
    cudaGetSymbolAddress((void**)&both,  g_both);
    cudaGetSymbolAddress((void**)&yh,    g_yh);
    cudaGetSymbolAddress((void**)&yl,    g_yl);
    cudaGetSymbolAddress((void**)&part,  g_part);
    cudaGetSymbolAddress((void**)&Wh,    g_Wh);
    cudaGetSymbolAddress((void**)&Wl,    g_Wl);
    cudaGetSymbolAddress((void**)&M0h,   g_M0h);
    cudaGetSymbolAddress((void**)&M0l,   g_M0l);
    cudaGetSymbolAddress((void**)&M1h,   g_M1h);
    cudaGetSymbolAddress((void**)&M1l,   g_M1l);
    cudaGetSymbolAddress((void**)&h0h,   g_h0h);
    cudaGetSymbolAddress((void**)&h0l,   g_h0l);
    cudaGetSymbolAddress((void**)&hid,   g_hid);

    // 1) pad + homogeneous augment
    pad_kernel<<<(HIDP * HIDP + 255) / 256, 256>>>(h2h_w, h2h_b, hidden);

    // 2) hand features (last frame only) -> feat pair
    hand_feat_kernel<<<1024, 128>>>(hand_data, l_conv_w, l_conv_b, r_conv_w, r_conv_b, tOff);

    // 3) dual fc GEMM -> both (fp32)
    mma_gemm<16, false, true, true, false, true, false><<<dim3(5, 16), 256>>>(
        1024, HF, FEAT, feath, featl, FEAT, l_fc_w, nullptr, nullptr, FEAT,
        l_fc_b, both, nullptr, nullptr, HF, r_fc_w, r_fc_b);

    // 4) conv2 + relu + pool3 -> y pair
    conv2pool_kernel<<<NB, 256>>>(conv2_w, conv2_b);

    // 5) l2 GEMM split-K=3 -> partials
    mma_gemm<32, false, true, false, true, false, false><<<dim3(8, 8, SPLITK), 256>>>(
        NB, HID, YK, yh, yl, YK, l2_w, nullptr, nullptr, YK,
        nullptr, part, nullptr, nullptr, HID, nullptr, nullptr);

    // 6) 5 squarings of augmented W (pair in, pair out): W->M0->M1->M0->M1->M0
    {
        const __nv_bfloat16 *sh = Wh, *sl = Wl;
        __nv_bfloat16 *dsth[5] = { M0h, M1h, M0h, M1h, M0h };
        __nv_bfloat16 *dstl[5] = { M0l, M1l, M0l, M1l, M0l };
        for (int i = 0; i < 5; ++i) {
            mma_gemm<32, true, false, false, false, false, true><<<dim3(8, 8), 256>>>(
                HIDP, HIDP, HIDP, sh, sl, HIDP, nullptr, sh, sl, HIDP,
                nullptr, nullptr, dsth[i], dstl[i], HIDP, nullptr, nullptr);
            sh = dsth[i]; sl = dstl[i];
        }
    }

    // 7) hidden_final (incl. bias via homogeneous col) -> d_out tail
    float* hidC = (out_size >= NB * OUT + NB * HID) ? ((float*)d_out) + NB * OUT : hid;
    mma_gemm<32, true, true, false, false, false, false><<<dim3(8, 8), 256>>>(
        NB, HID, HIDP, h0h, h0l, HIDP, nullptr, M0h, M0l, HIDP,
        nullptr, hidC, nullptr, nullptr, HID, nullptr, nullptr);

    // 8) fused split-K reduce + bias + RNN output
    out_kernel<<<NB, OUT * 32>>>(part, l2_b, hidC, out_w, out_b, (float*)d_out);
}

// round 4
// speedup vs baseline: 2.6328x; 1.6695x over previous
#include <cuda_runtime.h>
#include <cuda_bf16.h>

// ---------------------------------------------------------------------------
// ASLRNN3 sm_100a.
//  * only last frame feeds outs[-1]
//  * hidden recurrence is affine, independent of i2h -> homogeneous 501x501
//    power via 5 squarings (512-pad); chain runs on a SIDE STREAM overlapped
//    with the data front-end (hand conv / fc / conv2pool / l2 GEMM).
//  * all big GEMMs: bf16 hi/lo split 3-MMA, fp32 accum, cp.async 2-stage.
//  * chain epilogue writes M and M^T pairs so every GEMM uses the TRANSB path.
// ---------------------------------------------------------------------------

#define NB 512
#define FEAT 304
#define HF 300
#define YK 9504
#define HID 500
#define HIDP 512
#define OUT 10
#define SPLITK 3
#define SPLITLEN 3168   // 99*32

typedef __nv_bfloat16 bf;

// ---- scratch ----
__device__ bf g_feath[1024 * FEAT];
__device__ bf g_featl[1024 * FEAT];
__device__ float g_both[1024 * HF];
__device__ bf g_yh[NB * YK];
__device__ bf g_yl[NB * YK];
__device__ bf g_l2wh[HIDP * YK];
__device__ bf g_l2wl[HIDP * YK];
__device__ float g_part[SPLITK * NB * HID];
__device__ bf g_Wh [HIDP * HIDP];
__device__ bf g_Wl [HIDP * HIDP];
__device__ bf g_WTh[HIDP * HIDP];
__device__ bf g_WTl[HIDP * HIDP];
__device__ bf g_M0h[HIDP * HIDP];
__device__ bf g_M0l[HIDP * HIDP];
__device__ bf g_M0Th[HIDP * HIDP];
__device__ bf g_M0Tl[HIDP * HIDP];
__device__ bf g_M1h[HIDP * HIDP];
__device__ bf g_M1l[HIDP * HIDP];
__device__ bf g_M1Th[HIDP * HIDP];
__device__ bf g_M1Tl[HIDP * HIDP];
__device__ bf g_h0h[NB * HIDP];
__device__ bf g_h0l[NB * HIDP];
__device__ float g_hid[NB * HID];

#define MMA16816(c, a, b) asm volatile( \
    "mma.sync.aligned.m16n8k16.row.col.f32.bf16.bf16.f32 " \
    "{%0,%1,%2,%3},{%4,%5,%6,%7},{%8,%9},{%0,%1,%2,%3};\n" \
    : "+f"((c)[0]), "+f"((c)[1]), "+f"((c)[2]), "+f"((c)[3]) \
    : "r"((a)[0]), "r"((a)[1]), "r"((a)[2]), "r"((a)[3]), \
      "r"((b)[0]), "r"((b)[1]))

__device__ __forceinline__ unsigned ld32bf(const bf* p) {
    return *reinterpret_cast<const unsigned*>(p);
}
__device__ __forceinline__ void split_pair(float x, bf& h, bf& l) {
    h = __float2bfloat16(x);
    l = __float2bfloat16(x - __bfloat162float(h));
}
__device__ __forceinline__ void cp16(unsigned dst, const void* src) {
    asm volatile("cp.async.ca.shared.global [%0], [%1], 16;\n" :: "r"(dst), "l"(src));
}
#define CP_COMMIT asm volatile("cp.async.commit_group;\n")

// ---------------------------------------------------------------------------
// pair-pair GEMM, TRANSB only: C(M,N) = A(M,K) @ B(N,K)^T, A/B bf16 hi-lo pairs.
// cp.async 2-stage pipeline, BK=32. Buffers must have >= gridDim*64 rows and
// K%32==0 (per split chunk). SPLIT: gridDim.z partials into C.
// OUTPAIR: write bf16 pair + transposed pair (for the W-power chain).
// ---------------------------------------------------------------------------
template<bool SPLIT, bool OUTPAIR>
__global__ __launch_bounds__(256)
void pp_gemm(int M, int N, int K,
             const bf* __restrict__ Agh, const bf* __restrict__ Agl, int lda,
             const bf* __restrict__ Bgh, const bf* __restrict__ Bgl, int ldb,
             float* __restrict__ C, int ldc,
             bf* __restrict__ Cgh, bf* __restrict__ Cgl,
             bf* __restrict__ CghT, bf* __restrict__ CglT, int ldcp)
{
    constexpr int BK = 32, SA = 40;
    constexpr int ARRE = 64 * SA;              // elems per array
    __shared__ __align__(16) bf sm[2 * 4 * ARRE];
    const unsigned smb = (unsigned)__cvta_generic_to_shared(sm);
    constexpr unsigned ARRB = ARRE * 2;        // bytes
    constexpr unsigned STAGEB = 4 * ARRB;

    const int tid  = threadIdx.x;
    const int wid  = tid >> 5;
    const int lane = tid & 31;
    const int wm   = (wid >> 2) * 32;
    const int wn   = (wid & 3) * 16;
    const int lr   = lane >> 2;
    const int lc   = lane & 3;
    const int m0   = blockIdx.y * 64;
    const int n0   = blockIdx.x * 64;

    int kbeg = 0, kend = K;
    if (SPLIT) {
        kbeg = blockIdx.z * SPLITLEN;
        kend = min(K, kbeg + SPLITLEN);
        C += (size_t)blockIdx.z * (size_t)M * (size_t)ldc;
    }

    float acc[2][2][4] = {};

    const int ar = tid >> 2;            // 0..63
    const int ac = (tid & 3) * 8;       // 0,8,16,24

    auto issue = [&](int k0, int st) {
        const size_t ao = (size_t)(m0 + ar) * lda + k0 + ac;
        const size_t bo = (size_t)(n0 + ar) * ldb + k0 + ac;
        const unsigned d = smb + st * STAGEB + (unsigned)(ar * SA + ac) * 2;
        cp16(d,            Agh + ao);
        cp16(d + ARRB,     Agl + ao);
        cp16(d + 2 * ARRB, Bgh + bo);
        cp16(d + 3 * ARRB, Bgl + bo);
        CP_COMMIT;
    };

    const int nit = (kend - kbeg) / BK;
    issue(kbeg, 0);
    for (int i = 0; i < nit; ++i) {
        if (i + 1 < nit) {
            issue(kbeg + (i + 1) * BK, (i + 1) & 1);
            asm volatile("cp.async.wait_group 1;\n");
        } else {
            asm volatile("cp.async.wait_group 0;\n");
        }
        __syncthreads();

        const bf* base = sm + (i & 1) * 4 * ARRE;
        const bf* Ah = base;
        const bf* Al = base + ARRE;
        const bf* Bh = base + 2 * ARRE;
        const bf* Bl = base + 3 * ARRE;

        #pragma unroll
        for (int s = 0; s < 2; ++s) {
            const int kb = s * 16;
            unsigned a_h[2][4], a_l[2][4], b_h[2][2], b_l[2][2];
            #pragma unroll
            for (int mt = 0; mt < 2; ++mt) {
                const bf* p = Ah + (wm + mt * 16 + lr) * SA + kb + lc * 2;
                const bf* q = Al + (wm + mt * 16 + lr) * SA + kb + lc * 2;
                a_h[mt][0] = ld32bf(p);
                a_h[mt][1] = ld32bf(p + 8 * SA);
                a_h[mt][2] = ld32bf(p + 8);
                a_h[mt][3] = ld32bf(p + 8 * SA + 8);
                a_l[mt][0] = ld32bf(q);
                a_l[mt][1] = ld32bf(q + 8 * SA);
                a_l[mt][2] = ld32bf(q + 8);
                a_l[mt][3] = ld32bf(q + 8 * SA + 8);
            }
            #pragma unroll
            for (int nt = 0; nt < 2; ++nt) {
                const bf* p = Bh + (wn + nt * 8 + lr) * SA + kb + lc * 2;
                const bf* q = Bl + (wn + nt * 8 + lr) * SA + kb + lc * 2;
                b_h[nt][0] = ld32bf(p);
                b_h[nt][1] = ld32bf(p + 8);
                b_l[nt][0] = ld32bf(q);
                b_l[nt][1] = ld32bf(q + 8);
            }
            #pragma unroll
            for (int mt = 0; mt < 2; ++mt)
                #pragma unroll
                for (int nt = 0; nt < 2; ++nt) {
                    MMA16816(acc[mt][nt], a_h[mt], b_h[nt]);
                    MMA16816(acc[mt][nt], a_h[mt], b_l[nt]);
                    MMA16816(acc[mt][nt], a_l[mt], b_h[nt]);
                }
        }
        __syncthreads();
    }

    #pragma unroll
    for (int mt = 0; mt < 2; ++mt) {
        #pragma unroll
        for (int nt = 0; nt < 2; ++nt) {
            #pragma unroll
            for (int rr = 0; rr < 2; ++rr) {
                const int r = m0 + wm + mt * 16 + lr + rr * 8;
                #pragma unroll
                for (int j = 0; j < 2; ++j) {
                    const int c = n0 + wn + nt * 8 + lc * 2 + j;
                    if (c < N) {
                        float v = acc[mt][nt][rr * 2 + j];
                        if (OUTPAIR) {
                            bf h, l;
                            split_pair(v, h, l);
                            Cgh [(size_t)r * ldcp + c] = h;
                            Cgl [(size_t)r * ldcp + c] = l;
                            CghT[(size_t)c * ldcp + r] = h;
                            CglT[(size_t)c * ldcp + r] = l;
                        } else {
                            C[(size_t)r * ldc + c] = v;
                        }
                    }
                }
            }
        }
    }
}

// ---------------------------------------------------------------------------
// fc GEMM: C(1024,300) = feat-pair @ B^T + bias, relu; fp32 B (dual weights).
// BK=16, single-buffered (small, overlapped under the chain).
// ---------------------------------------------------------------------------
__global__ __launch_bounds__(256)
void fc_gemm(const bf* __restrict__ Agh, const bf* __restrict__ Agl,
             const float* __restrict__ Bf, const float* __restrict__ bias,
             const float* __restrict__ Bf2, const float* __restrict__ bias2,
             float* __restrict__ C)
{
    constexpr int BK = 16, SA = 24, ARRE = 64 * SA;
    __shared__ __align__(16) bf sm[4 * ARRE];
    bf* Ah = sm;
    bf* Al = sm + ARRE;
    bf* Bh = sm + 2 * ARRE;
    bf* Bl = sm + 3 * ARRE;

    const int tid  = threadIdx.x;
    const int wid  = tid >> 5;
    const int lane = tid & 31;
    const int wm   = (wid >> 2) * 32;
    const int wn   = (wid & 3) * 16;
    const int lr   = lane >> 2;
    const int lc   = lane & 3;
    const int m0   = blockIdx.y * 64;
    const int n0   = blockIdx.x * 64;
    const int N = HF, K = FEAT;

    if (blockIdx.y >= (gridDim.y >> 1)) { Bf = Bf2; bias = bias2; }

    float acc[2][2][4] = {};
    const int ar = tid >> 2;
    const int ac = (tid & 3) * 4;

    for (int k0 = 0; k0 < K; k0 += BK) {
        {
            const size_t off = (size_t)(m0 + ar) * K + k0 + ac;
            *reinterpret_cast<uint2*>(Ah + ar * SA + ac) =
                *reinterpret_cast<const uint2*>(Agh + off);
            *reinterpret_cast<uint2*>(Al + ar * SA + ac) =
                *reinterpret_cast<const uint2*>(Agl + off);
        }
        {
            float4 v = make_float4(0.f, 0.f, 0.f, 0.f);
            if (n0 + ar < N)
                v = *reinterpret_cast<const float4*>(&Bf[(size_t)(n0 + ar) * K + k0 + ac]);
            split_pair(v.x, Bh[ar * SA + ac + 0], Bl[ar * SA + ac + 0]);
            split_pair(v.y, Bh[ar * SA + ac + 1], Bl[ar * SA + ac + 1]);
            split_pair(v.z, Bh[ar * SA + ac + 2], Bl[ar * SA + ac + 2]);
            split_pair(v.w, Bh[ar * SA + ac + 3], Bl[ar * SA + ac + 3]);
        }
        __syncthreads();

        unsigned a_h[2][4], a_l[2][4], b_h[2][2], b_l[2][2];
        #pragma unroll
        for (int mt = 0; mt < 2; ++mt) {
            const bf* p = Ah + (wm + mt * 16 + lr) * SA + lc * 2;
            const bf* q = Al + (wm + mt * 16 + lr) * SA + lc * 2;
            a_h[mt][0] = ld32bf(p);
            a_h[mt][1] = ld32bf(p + 8 * SA);
            a_h[mt][2] = ld32bf(p + 8);
            a_h[mt][3] = ld32bf(p + 8 * SA + 8);
            a_l[mt][0] = ld32bf(q);
            a_l[mt][1] = ld32bf(q + 8 * SA);
            a_l[mt][2] = ld32bf(q + 8);
            a_l[mt][3] = ld32bf(q + 8 * SA + 8);
        }
        #pragma unroll
        for (int nt = 0; nt < 2; ++nt) {
            const bf* p = Bh + (wn + nt * 8 + lr) * SA + lc * 2;
            const bf* q = Bl + (wn + nt * 8 + lr) * SA + lc * 2;
            b_h[nt][0] = ld32bf(p);
            b_h[nt][1] = ld32bf(p + 8);
            b_l[nt][0] = ld32bf(q);
            b_l[nt][1] = ld32bf(q + 8);
        }
        #pragma unroll
        for (int mt = 0; mt < 2; ++mt)
            #pragma unroll
            for (int nt = 0; nt < 2; ++nt) {
                MMA16816(acc[mt][nt], a_h[mt], b_h[nt]);
                MMA16816(acc[mt][nt], a_h[mt], b_l[nt]);
                MMA16816(acc[mt][nt], a_l[mt], b_h[nt]);
            }
        __syncthreads();
    }

    #pragma unroll
    for (int mt = 0; mt < 2; ++mt)
        #pragma unroll
        for (int nt = 0; nt < 2; ++nt)
            #pragma unroll
            for (int rr = 0; rr < 2; ++rr) {
                const int r = m0 + wm + mt * 16 + lr + rr * 8;
                #pragma unroll
                for (int j = 0; j < 2; ++j) {
                    const int c = n0 + wn + nt * 8 + lc * 2 + j;
                    if (c < N) {
                        float v = fmaxf(acc[mt][nt][rr * 2 + j] + bias[c], 0.f);
                        C[(size_t)r * HF + c] = v;
                    }
                }
            }
}

// ---------------------------------------------------------------------------
// Pad + homogeneous augment: W pair, W^T pair, h0 pair
__global__ void pad_kernel(const float* __restrict__ W,
                           const float* __restrict__ b,
                           const float* __restrict__ h0)
{
    int idx = blockIdx.x * blockDim.x + threadIdx.x;
    if (idx >= HIDP * HIDP) return;
    int r = idx >> 9, c = idx & (HIDP - 1);
    float wv = 0.f;
    if (r < HID) {
        if (c < HID) wv = W[r * HID + c];
        else if (c == HID) wv = b[r];
    } else if (r == HID && c == HID) wv = 1.f;
    bf h, l;
    split_pair(wv, h, l);
    g_Wh[idx] = h;  g_Wl[idx] = l;
    g_WTh[c * HIDP + r] = h;  g_WTl[c * HIDP + r] = l;
    float hv = (c < HID) ? h0[r * HID + c] : (c == HID ? 1.f : 0.f);
    split_pair(hv, g_h0h[idx], g_h0l[idx]);
}

// Split l2_w (500,9504) fp32 -> 512-row padded bf16 pair
__global__ void split_w_kernel(const float* __restrict__ w)
{
    int t = blockIdx.x * blockDim.x + threadIdx.x;
    int e = t * 4;
    if (e >= HIDP * YK) return;
    int r = e / YK, c = e - r * YK;
    if (r < HID) {
        float4 v = *reinterpret_cast<const float4*>(&w[(size_t)r * YK + c]);
        split_pair(v.x, g_l2wh[e + 0], g_l2wl[e + 0]);
        split_pair(v.y, g_l2wh[e + 1], g_l2wl[e + 1]);
        split_pair(v.z, g_l2wh[e + 2], g_l2wl[e + 2]);
        split_pair(v.w, g_l2wh[e + 3], g_l2wl[e + 3]);
    } else {
        *reinterpret_cast<uint2*>(&g_l2wh[e]) = make_uint2(0, 0);
        *reinterpret_cast<uint2*>(&g_l2wl[e]) = make_uint2(0, 0);
    }
}

// hand branch: conv1d(k=2,2->16) + relu + pool2 -> feat pair (1024 x 304)
__global__ void hand_feat_kernel(const float* __restrict__ hd,
                                 const float* __restrict__ lcw, const float* __restrict__ lcb,
                                 const float* __restrict__ rcw, const float* __restrict__ rcb,
                                 int tOff)
{
    const int s    = blockIdx.x;
    const int n    = s & (NB - 1);
    const int hand = s >> 9;
    const float* x  = hd + tOff + n * 84 + hand * 42;
    const float* cw = hand ? rcw : lcw;
    const float* cb = hand ? rcb : lcb;

    __shared__ float xs[42];
    __shared__ float z[16 * 20];
    const int tid = threadIdx.x;
    if (tid < 42) xs[tid] = x[tid];
    __syncthreads();

    for (int idx = tid; idx < 320; idx += 128) {
        int o = idx / 20, j = idx % 20;
        float v = cb[o]
                + cw[o * 4 + 0] * xs[2 * j]
                + cw[o * 4 + 1] * xs[2 * j + 2]
                + cw[o * 4 + 2] * xs[2 * j + 1]
                + cw[o * 4 + 3] * xs[2 * j + 3];
        z[o * 20 + j] = fmaxf(v, 0.f);
    }
    __syncthreads();

    for (int idx = tid; idx < FEAT; idx += 128) {
        int o = idx / 19, j = idx % 19;
        float v = fmaxf(z[o * 20 + j], z[o * 20 + j + 1]);
        split_pair(v, g_feath[(size_t)s * FEAT + idx], g_featl[(size_t)s * FEAT + idx]);
    }
}

// conv2(k=2,2->32) + relu + pool3 -> y pair; one block per sample
__global__ __launch_bounds__(256)
void conv2pool_kernel(const float* __restrict__ w2, const float* __restrict__ b2)
{
    __shared__ float slo[HF], sro[HF], sw[128], sb[32];
    const int n = blockIdx.x;
    const int tid = threadIdx.x;
    for (int i = tid; i < HF; i += 256) {
        slo[i] = g_both[(size_t)n * HF + i];
        sro[i] = g_both[(size_t)(NB + n) * HF + i];
    }
    if (tid < 128) sw[tid] = w2[tid];
    if (tid < 32)  sb[tid] = b2[tid];
    __syncthreads();

    for (int k = tid; k < YK; k += 256) {
        const int o = k / 297, jj = k - o * 297;
        const float w00 = sw[o * 4 + 0], w01 = sw[o * 4 + 1];
        const float w10 = sw[o * 4 + 2], w11 = sw[o * 4 + 3];
        const float bb = sb[o];
        float l0 = slo[jj], l1 = slo[jj + 1], l2v = slo[jj + 2], l3 = slo[jj + 3];
        float r0 = sro[jj], r1 = sro[jj + 1], r2v = sro[jj + 2], r3 = sro[jj + 3];
        float z0 = bb + w00 * l0  + w01 * l1  + w10 * r0  + w11 * r1;
        float z1 = bb + w00 * l1  + w01 * l2v + w10 * r1  + w11 * r2v;
        float z2 = bb + w00 * l2v + w01 * l3  + w10 * r2v + w11 * r3;
        float v = fmaxf(fmaxf(z0, z1), fmaxf(z2, 0.f));
        split_pair(v, g_yh[(size_t)n * YK + k], g_yl[(size_t)n * YK + k]);
    }
}

// out = relu((part0+part1+part2+l2_b + hidden) @ out_w^T + out_b)
__global__ void out_kernel(const float* __restrict__ part,
                           const float* __restrict__ l2b,
                           const float* __restrict__ hid,
                           const float* __restrict__ ow,
                           const float* __restrict__ ob,
                           float* __restrict__ out)
{
    const int n    = blockIdx.x;
    const int m    = threadIdx.x >> 5;
    const int lane = threadIdx.x & 31;
    const float* p0 = part + (size_t)n * HID;
    const float* p1 = p0 + (size_t)NB * HID;
    const float* p2 = p1 + (size_t)NB * HID;
    const float* h  = hid + (size_t)n * HID;
    const float* w  = ow + (size_t)m * HID;
    float s = 0.f;
    for (int k = lane; k < HID; k += 32)
        s += (p0[k] + p1[k] + p2[k] + l2b[k] + h[k]) * w[k];
    #pragma unroll
    for (int o = 16; o; o >>= 1) s += __shfl_down_sync(0xffffffffu, s, o);
    if (lane == 0) out[n * OUT + m] = fmaxf(s + ob[m], 0.f);
}

// ---------------------------------------------------------------------------
static cudaStream_t s_side = nullptr;
static cudaEvent_t  s_evF  = nullptr;
static cudaEvent_t  s_evJ  = nullptr;

extern "C" void kernel_launch(void* const* d_in, const int* in_sizes, int n_in,
                              void* d_out, int out_size)
{
    if (!s_side) {
        cudaStreamCreateWithFlags(&s_side, cudaStreamNonBlocking);
        cudaEventCreateWithFlags(&s_evF, cudaEventDisableTiming);
        cudaEventCreateWithFlags(&s_evJ, cudaEventDisableTiming);
    }

    const float* hand_data = (const float*)d_in[0];
    const float* hidden    = (const float*)d_in[1];
    const float* l_conv_w  = (const float*)d_in[2];
    const float* l_conv_b  = (const float*)d_in[3];
    const float* l_fc_w    = (const float*)d_in[4];
    const float* l_fc_b    = (const float*)d_in[5];
    const float* r_conv_w  = (const float*)d_in[6];
    const float* r_conv_b  = (const float*)d_in[7];
    const float* r_fc_w    = (const float*)d_in[8];
    const float* r_fc_b    = (const float*)d_in[9];
    const float* conv2_w   = (const float*)d_in[10];
    const float* conv2_b   = (const float*)d_in[11];
    const float* l2_w      = (const float*)d_in[12];
    const float* l2_b      = (const float*)d_in[13];
    const float* h2h_w     = (const float*)d_in[14];
    const float* h2h_b     = (const float*)d_in[15];
    const float* out_w     = (const float*)d_in[16];
    const float* out_b     = (const float*)d_in[17];

    const int T    = in_sizes[0] / (NB * 84);
    const int tOff = (T - 1) * NB * 84;

    bf *feath, *featl, *yh, *yl, *l2wh, *l2wl;
    bf *Wh, *Wl, *WTh, *WTl, *M0h, *M0l, *M0Th, *M0Tl, *M1h, *M1l, *M1Th, *M1Tl;
    bf *h0h, *h0l;
    float *both, *part, *hid;
    cudaGetSymbolAddress((void**)&feath, g_feath);
    cudaGetSymbolAddress((void**)&featl, g_featl);
    cudaGetSymbolAddress((void**)&both,  g_both);
    cudaGetSymbolAddress((void**)&yh,    g_yh);
    cudaGetSymbolAddress((void**)&yl,    g_yl);
    cudaGetSymbolAddress((void**)&l2wh,  g_l2wh);
    cudaGetSymbolAddress((void**)&l2wl,  g_l2wl);
    cudaGetSymbolAddress((void**)&part,  g_part);
    cudaGetSymbolAddress((void**)&Wh,    g_Wh);
    cudaGetSymbolAddress((void**)&Wl,    g_Wl);
    cudaGetSymbolAddress((void**)&WTh,   g_WTh);
    cudaGetSymbolAddress((void**)&WTl,   g_WTl);
    cudaGetSymbolAddress((void**)&M0h,   g_M0h);
    cudaGetSymbolAddress((void**)&M0l,   g_M0l);
    cudaGetSymbolAddress((void**)&M0Th,  g_M0Th);
    cudaGetSymbolAddress((void**)&M0Tl,  g_M0Tl);
    cudaGetSymbolAddress((void**)&M1h,   g_M1h);
    cudaGetSymbolAddress((void**)&M1l,   g_M1l);
    cudaGetSymbolAddress((void**)&M1Th,  g_M1Th);
    cudaGetSymbolAddress((void**)&M1Tl,  g_M1Tl);
    cudaGetSymbolAddress((void**)&h0h,   g_h0h);
    cudaGetSymbolAddress((void**)&h0l,   g_h0l);
    cudaGetSymbolAddress((void**)&hid,   g_hid);

    float* hidC = (out_size >= NB * OUT + NB * HID) ? ((float*)d_out) + NB * OUT : hid;

    // 1) pad + homogeneous augment (main stream)
    pad_kernel<<<(HIDP * HIDP + 255) / 256, 256>>>(h2h_w, h2h_b, hidden);

    // fork: side stream runs the W-power chain + hidden GEMM
    cudaEventRecord(s_evF, 0);
    cudaStreamWaitEvent(s_side, s_evF, 0);

    {   // 5 squarings: A=Mi (row pair), B=Mi^T pair; out: Mi+1 pair + T pair
        const bf *sh = Wh, *sl = Wl, *sth = WTh, *stl = WTl;
        bf* dh [5] = { M0h,  M1h,  M0h,  M1h,  M0h  };
        bf* dl [5] = { M0l,  M1l,  M0l,  M1l,  M0l  };
        bf* dth[5] = { M0Th, M1Th, M0Th, M1Th, M0Th };
        bf* dtl[5] = { M0Tl, M1Tl, M0Tl, M1Tl, M0Tl };
        for (int i = 0; i < 5; ++i) {
            pp_gemm<false, true><<<dim3(8, 8), 256, 0, s_side>>>(
                HIDP, HIDP, HIDP, sh, sl, HIDP, sth, stl, HIDP,
                nullptr, 0, dh[i], dl[i], dth[i], dtl[i], HIDP);
            sh = dh[i]; sl = dl[i]; sth = dth[i]; stl = dtl[i];
        }
        // hidden_final = h0aug @ M32^T (bias via homogeneous col) -> d_out tail
        pp_gemm<false, false><<<dim3(8, 8), 256, 0, s_side>>>(
            NB, HID, HIDP, h0h, h0l, HIDP, M0h, M0l, HIDP,
            hidC, HID, nullptr, nullptr, nullptr, nullptr, 0);
    }
    cudaEventRecord(s_evJ, s_side);

    // main stream: data front-end
    split_w_kernel<<<(HIDP * YK / 4 + 255) / 256, 256>>>(l2_w);
    hand_feat_kernel<<<1024, 128>>>(hand_data, l_conv_w, l_conv_b, r_conv_w, r_conv_b, tOff);
    fc_gemm<<<dim3(5, 16), 256>>>(feath, featl, l_fc_w, l_fc_b, r_fc_w, r_fc_b, both);
    conv2pool_kernel<<<NB, 256>>>(conv2_w, conv2_b);
    pp_gemm<true, false><<<dim3(8, 8, SPLITK), 256>>>(
        NB, HID, YK, yh, yl, YK, l2wh, l2wl, YK,
        part, HID, nullptr, nullptr, nullptr, nullptr, 0);

    // join + fused split-K reduce + RNN output
    cudaStreamWaitEvent(0, s_evJ, 0);
    out_kernel<<<NB, OUT * 32>>>(part, l2_b, hidC, out_w, out_b, (float*)d_out);
}

// round 5
// speedup vs baseline: 3.0216x; 1.1477x over previous
#include <cuda_runtime.h>
#include <cuda_bf16.h>

// ---------------------------------------------------------------------------
// ASLRNN3 sm_100a.
//  * only last frame feeds outs[-1]
//  * hidden recurrence: affine, i2h-independent -> homogeneous 501x501 power
//    via 5 squarings (512-pad), all split-K=4 + reduce_split, on a side stream
//    overlapped with the data front-end; l2_w split runs on a third stream.
//  * all big GEMMs: bf16 hi/lo 3-MMA, fp32 accum, cp.async 2-stage.
// ---------------------------------------------------------------------------

#define NB 512
#define FEAT 304
#define HF 300
#define YK 9504
#define HID 500
#define HIDP 512
#define OUT 10
#define L2S 9          // l2 split-K factor  (9504 = 9*1056, 1056 = 33*32)
#define L2LEN 1056
#define CHS 4          // chain split-K      (512 = 4*128)
#define CHLEN 128

typedef __nv_bfloat16 bf;

// ---- scratch ----
__device__ bf g_feath[1024 * FEAT];
__device__ bf g_featl[1024 * FEAT];
__device__ float g_both[1024 * HF];
__device__ bf g_yh[NB * YK];
__device__ bf g_yl[NB * YK];
__device__ bf g_l2wh[HIDP * YK];
__device__ bf g_l2wl[HIDP * YK];
__device__ float g_part[L2S * NB * HID];
__device__ float g_cpart[CHS * HIDP * HIDP];
__device__ float g_hpart[CHS * NB * HID];
__device__ bf g_Wh [HIDP * HIDP];
__device__ bf g_Wl [HIDP * HIDP];
__device__ bf g_WTh[HIDP * HIDP];
__device__ bf g_WTl[HIDP * HIDP];
__device__ bf g_M0h[HIDP * HIDP];
__device__ bf g_M0l[HIDP * HIDP];
__device__ bf g_M0Th[HIDP * HIDP];
__device__ bf g_M0Tl[HIDP * HIDP];
__device__ bf g_M1h[HIDP * HIDP];
__device__ bf g_M1l[HIDP * HIDP];
__device__ bf g_M1Th[HIDP * HIDP];
__device__ bf g_M1Tl[HIDP * HIDP];
__device__ bf g_h0h[NB * HIDP];
__device__ bf g_h0l[NB * HIDP];
__device__ float g_hid[NB * HID];

#define MMA16816(c, a, b) asm volatile( \
    "mma.sync.aligned.m16n8k16.row.col.f32.bf16.bf16.f32 " \
    "{%0,%1,%2,%3},{%4,%5,%6,%7},{%8,%9},{%0,%1,%2,%3};\n" \
    : "+f"((c)[0]), "+f"((c)[1]), "+f"((c)[2]), "+f"((c)[3]) \
    : "r"((a)[0]), "r"((a)[1]), "r"((a)[2]), "r"((a)[3]), \
      "r"((b)[0]), "r"((b)[1]))

__device__ __forceinline__ unsigned ld32bf(const bf* p) {
    return *reinterpret_cast<const unsigned*>(p);
}
__device__ __forceinline__ void split_pair(float x, bf& h, bf& l) {
    h = __float2bfloat16(x);
    l = __float2bfloat16(x - __bfloat162float(h));
}
__device__ __forceinline__ void cp16(unsigned dst, const void* src) {
    asm volatile("cp.async.ca.shared.global [%0], [%1], 16;\n" :: "r"(dst), "l"(src));
}
#define CP_COMMIT asm volatile("cp.async.commit_group;\n")

// ---------------------------------------------------------------------------
// pair-pair GEMM: C(M,N) fp32 = A(M,K) @ B(N,K)^T, A/B bf16 hi-lo pairs.
// cp.async 2-stage, BK=32. SPLIT: gridDim.z chunks of splitLen, partial per z.
// K chunk % 32 == 0; B buffers must have >= gridDim.x*64 rows.
// ---------------------------------------------------------------------------
template<bool SPLIT>
__global__ __launch_bounds__(256)
void pp_gemm(int M, int N, int K,
             const bf* __restrict__ Agh, const bf* __restrict__ Agl, int lda,
             const bf* __restrict__ Bgh, const bf* __restrict__ Bgl, int ldb,
             float* __restrict__ C, int ldc, int splitLen)
{
    constexpr int BK = 32, SA = 40;
    constexpr int ARRE = 64 * SA;
    __shared__ __align__(16) bf sm[2 * 4 * ARRE];
    const unsigned smb = (unsigned)__cvta_generic_to_shared(sm);
    constexpr unsigned ARRB = ARRE * 2;
    constexpr unsigned STAGEB = 4 * ARRB;

    const int tid  = threadIdx.x;
    const int wid  = tid >> 5;
    const int lane = tid & 31;
    const int wm   = (wid >> 2) * 32;
    const int wn   = (wid & 3) * 16;
    const int lr   = lane >> 2;
    const int lc   = lane & 3;
    const int m0   = blockIdx.y * 64;
    const int n0   = blockIdx.x * 64;

    int kbeg = 0, kend = K;
    if (SPLIT) {
        kbeg = blockIdx.z * splitLen;
        kend = min(K, kbeg + splitLen);
        C += (size_t)blockIdx.z * (size_t)M * (size_t)ldc;
    }

    float acc[2][2][4] = {};
    const int ar = tid >> 2;
    const int ac = (tid & 3) * 8;

    auto issue = [&](int k0, int st) {
        const size_t ao = (size_t)(m0 + ar) * lda + k0 + ac;
        const size_t bo = (size_t)(n0 + ar) * ldb + k0 + ac;
        const unsigned d = smb + st * STAGEB + (unsigned)(ar * SA + ac) * 2;
        cp16(d,            Agh + ao);
        cp16(d + ARRB,     Agl + ao);
        cp16(d + 2 * ARRB, Bgh + bo);
        cp16(d + 3 * ARRB, Bgl + bo);
        CP_COMMIT;
    };

    const int nit = (kend - kbeg) / BK;
    issue(kbeg, 0);
    for (int i = 0; i < nit; ++i) {
        if (i + 1 < nit) {
            issue(kbeg + (i + 1) * BK, (i + 1) & 1);
            asm volatile("cp.async.wait_group 1;\n");
        } else {
            asm volatile("cp.async.wait_group 0;\n");
        }
        __syncthreads();

        const bf* base = sm + (i & 1) * 4 * ARRE;
        const bf* Ah = base;
        const bf* Al = base + ARRE;
        const bf* Bh = base + 2 * ARRE;
        const bf* Bl = base + 3 * ARRE;

        #pragma unroll
        for (int s = 0; s < 2; ++s) {
            const int kb = s * 16;
            unsigned a_h[2][4], a_l[2][4], b_h[2][2], b_l[2][2];
            #pragma unroll
            for (int mt = 0; mt < 2; ++mt) {
                const bf* p = Ah + (wm + mt * 16 + lr) * SA + kb + lc * 2;
                const bf* q = Al + (wm + mt * 16 + lr) * SA + kb + lc * 2;
                a_h[mt][0] = ld32bf(p);
                a_h[mt][1] = ld32bf(p + 8 * SA);
                a_h[mt][2] = ld32bf(p + 8);
                a_h[mt][3] = ld32bf(p + 8 * SA + 8);
                a_l[mt][0] = ld32bf(q);
                a_l[mt][1] = ld32bf(q + 8 * SA);
                a_l[mt][2] = ld32bf(q + 8);
                a_l[mt][3] = ld32bf(q + 8 * SA + 8);
            }
            #pragma unroll
            for (int nt = 0; nt < 2; ++nt) {
                const bf* p = Bh + (wn + nt * 8 + lr) * SA + kb + lc * 2;
                const bf* q = Bl + (wn + nt * 8 + lr) * SA + kb + lc * 2;
                b_h[nt][0] = ld32bf(p);
                b_h[nt][1] = ld32bf(p + 8);
                b_l[nt][0] = ld32bf(q);
                b_l[nt][1] = ld32bf(q + 8);
            }
            #pragma unroll
            for (int mt = 0; mt < 2; ++mt)
                #pragma unroll
                for (int nt = 0; nt < 2; ++nt) {
                    MMA16816(acc[mt][nt], a_h[mt], b_h[nt]);
                    MMA16816(acc[mt][nt], a_h[mt], b_l[nt]);
                    MMA16816(acc[mt][nt], a_l[mt], b_h[nt]);
                }
        }
        __syncthreads();
    }

    #pragma unroll
    for (int mt = 0; mt < 2; ++mt)
        #pragma unroll
        for (int nt = 0; nt < 2; ++nt)
            #pragma unroll
            for (int rr = 0; rr < 2; ++rr) {
                const int r = m0 + wm + mt * 16 + lr + rr * 8;
                #pragma unroll
                for (int j = 0; j < 2; ++j) {
                    const int c = n0 + wn + nt * 8 + lc * 2 + j;
                    if (c < N) C[(size_t)r * ldc + c] = acc[mt][nt][rr * 2 + j];
                }
            }
}

// ---------------------------------------------------------------------------
// reduce CHS fp32 partials -> bf16 pair (+ optional transposed pair), 512x512
template<bool WRITET>
__global__ __launch_bounds__(256)
void reduce_split(const float* __restrict__ part,
                  bf* __restrict__ Dh, bf* __restrict__ Dl,
                  bf* __restrict__ DTh, bf* __restrict__ DTl)
{
    __shared__ bf th[32][33], tl[32][33];
    const int bx = blockIdx.x * 32, by = blockIdx.y * 32;
    const int x = threadIdx.x & 31;
    const int y0 = threadIdx.x >> 5;           // 0..7
    #pragma unroll
    for (int dy = 0; dy < 32; dy += 8) {
        const int r = by + y0 + dy, c = bx + x;
        const size_t idx = (size_t)r * HIDP + c;
        float v = part[idx];
        #pragma unroll
        for (int s = 1; s < CHS; ++s) v += part[(size_t)s * HIDP * HIDP + idx];
        bf h, l;
        split_pair(v, h, l);
        Dh[idx] = h; Dl[idx] = l;
        th[y0 + dy][x] = h; tl[y0 + dy][x] = l;
    }
    if (WRITET) {
        __syncthreads();
        #pragma unroll
        for (int dy = 0; dy < 32; dy += 8) {
            const int r = bx + y0 + dy, c = by + x;
            const size_t idx = (size_t)r * HIDP + c;
            DTh[idx] = th[x][y0 + dy];
            DTl[idx] = tl[x][y0 + dy];
        }
    }
}

// ---------------------------------------------------------------------------
// fc GEMM: C(1024,300) = feat-pair @ B^T + bias, relu; fp32 dual weights.
__global__ __launch_bounds__(256)
void fc_gemm(const bf* __restrict__ Agh, const bf* __restrict__ Agl,
             const float* __restrict__ Bf, const float* __restrict__ bias,
             const float* __restrict__ Bf2, const float* __restrict__ bias2,
             float* __restrict__ C)
{
    constexpr int BK = 16, SA = 24, ARRE = 64 * SA;
    __shared__ __align__(16) bf sm[4 * ARRE];
    bf* Ah = sm;
    bf* Al = sm + ARRE;
    bf* Bh = sm + 2 * ARRE;
    bf* Bl = sm + 3 * ARRE;

    const int tid  = threadIdx.x;
    const int wid  = tid >> 5;
    const int lane = tid & 31;
    const int wm   = (wid >> 2) * 32;
    const int wn   = (wid & 3) * 16;
    const int lr   = lane >> 2;
    const int lc   = lane & 3;
    const int m0   = blockIdx.y * 64;
    const int n0   = blockIdx.x * 64;
    const int N = HF, K = FEAT;

    if (blockIdx.y >= (gridDim.y >> 1)) { Bf = Bf2; bias = bias2; }

    float acc[2][2][4] = {};
    const int ar = tid >> 2;
    const int ac = (tid & 3) * 4;

    for (int k0 = 0; k0 < K; k0 += BK) {
        {
            const size_t off = (size_t)(m0 + ar) * K + k0 + ac;
            *reinterpret_cast<uint2*>(Ah + ar * SA + ac) =
                *reinterpret_cast<const uint2*>(Agh + off);
            *reinterpret_cast<uint2*>(Al + ar * SA + ac) =
                *reinterpret_cast<const uint2*>(Agl + off);
        }
        {
            float4 v = make_float4(0.f, 0.f, 0.f, 0.f);
            if (n0 + ar < N)
                v = *reinterpret_cast<const float4*>(&Bf[(size_t)(n0 + ar) * K + k0 + ac]);
            split_pair(v.x, Bh[ar * SA + ac + 0], Bl[ar * SA + ac + 0]);
            split_pair(v.y, Bh[ar * SA + ac + 1], Bl[ar * SA + ac + 1]);
            split_pair(v.z, Bh[ar * SA + ac + 2], Bl[ar * SA + ac + 2]);
            split_pair(v.w, Bh[ar * SA + ac + 3], Bl[ar * SA + ac + 3]);
        }
        __syncthreads();

        unsigned a_h[2][4], a_l[2][4], b_h[2][2], b_l[2][2];
        #pragma unroll
        for (int mt = 0; mt < 2; ++mt) {
            const bf* p = Ah + (wm + mt * 16 + lr) * SA + lc * 2;
            const bf* q = Al + (wm + mt * 16 + lr) * SA + lc * 2;
            a_h[mt][0] = ld32bf(p);
            a_h[mt][1] = ld32bf(p + 8 * SA);
            a_h[mt][2] = ld32bf(p + 8);
            a_h[mt][3] = ld32bf(p + 8 * SA + 8);
            a_l[mt][0] = ld32bf(q);
            a_l[mt][1] = ld32bf(q + 8 * SA);
            a_l[mt][2] = ld32bf(q + 8);
            a_l[mt][3] = ld32bf(q + 8 * SA + 8);
        }
        #pragma unroll
        for (int nt = 0; nt < 2; ++nt) {
            const bf* p = Bh + (wn + nt * 8 + lr) * SA + lc * 2;
            const bf* q = Bl + (wn + nt * 8 + lr) * SA + lc * 2;
            b_h[nt][0] = ld32bf(p);
            b_h[nt][1] = ld32bf(p + 8);
            b_l[nt][0] = ld32bf(q);
            b_l[nt][1] = ld32bf(q + 8);
        }
        #pragma unroll
        for (int mt = 0; mt < 2; ++mt)
            #pragma unroll
            for (int nt = 0; nt < 2; ++nt) {
                MMA16816(acc[mt][nt], a_h[mt], b_h[nt]);
                MMA16816(acc[mt][nt], a_h[mt], b_l[nt]);
                MMA16816(acc[mt][nt], a_l[mt], b_h[nt]);
            }
        __syncthreads();
    }

    #pragma unroll
    for (int mt = 0; mt < 2; ++mt)
        #pragma unroll
        for (int nt = 0; nt < 2; ++nt)
            #pragma unroll
            for (int rr = 0; rr < 2; ++rr) {
                const int r = m0 + wm + mt * 16 + lr + rr * 8;
                #pragma unroll
                for (int j = 0; j < 2; ++j) {
                    const int c = n0 + wn + nt * 8 + lc * 2 + j;
                    if (c < N)
                        C[(size_t)r * HF + c] = fmaxf(acc[mt][nt][rr * 2 + j] + bias[c], 0.f);
                }
            }
}

// ---------------------------------------------------------------------------
__global__ void pad_kernel(const float* __restrict__ W,
                           const float* __restrict__ b,
                           const float* __restrict__ h0)
{
    int idx = blockIdx.x * blockDim.x + threadIdx.x;
    if (idx >= HIDP * HIDP) return;
    int r = idx >> 9, c = idx & (HIDP - 1);
    float wv = 0.f;
    if (r < HID) {
        if (c < HID) wv = W[r * HID + c];
        else if (c == HID) wv = b[r];
    } else if (r == HID && c == HID) wv = 1.f;
    bf h, l;
    split_pair(wv, h, l);
    g_Wh[idx] = h;  g_Wl[idx] = l;
    g_WTh[c * HIDP + r] = h;  g_WTl[c * HIDP + r] = l;
    float hv = (c < HID) ? h0[r * HID + c] : (c == HID ? 1.f : 0.f);
    split_pair(hv, g_h0h[idx], g_h0l[idx]);
}

// Split l2_w (500,9504) fp32 -> 512-row padded bf16 pair
__global__ void split_w_kernel(const float* __restrict__ w)
{
    int t = blockIdx.x * blockDim.x + threadIdx.x;
    int e = t * 4;
    if (e >= HIDP * YK) return;
    int r = e / YK, c = e - r * YK;
    if (r < HID) {
        float4 v = *reinterpret_cast<const float4*>(&w[(size_t)r * YK + c]);
        split_pair(v.x, g_l2wh[e + 0], g_l2wl[e + 0]);
        split_pair(v.y, g_l2wh[e + 1], g_l2wl[e + 1]);
        split_pair(v.z, g_l2wh[e + 2], g_l2wl[e + 2]);
        split_pair(v.w, g_l2wh[e + 3], g_l2wl[e + 3]);
    } else {
        *reinterpret_cast<uint2*>(&g_l2wh[e]) = make_uint2(0, 0);
        *reinterpret_cast<uint2*>(&g_l2wl[e]) = make_uint2(0, 0);
    }
}

// hand branch: conv1d(k=2,2->16) + relu + pool2 -> feat pair
__global__ void hand_feat_kernel(const float* __restrict__ hd,
                                 const float* __restrict__ lcw, const float* __restrict__ lcb,
                                 const float* __restrict__ rcw, const float* __restrict__ rcb,
                                 int tOff)
{
    const int s    = blockIdx.x;
    const int n    = s & (NB - 1);
    const int hand = s >> 9;
    const float* x  = hd + tOff + n * 84 + hand * 42;
    const float* cw = hand ? rcw : lcw;
    const float* cb = hand ? rcb : lcb;

    __shared__ float xs[42];
    __shared__ float z[16 * 20];
    const int tid = threadIdx.x;
    if (tid < 42) xs[tid] = x[tid];
    __syncthreads();

    for (int idx = tid; idx < 320; idx += 128) {
        int o = idx / 20, j = idx % 20;
        float v = cb[o]
                + cw[o * 4 + 0] * xs[2 * j]
                + cw[o * 4 + 1] * xs[2 * j + 2]
                + cw[o * 4 + 2] * xs[2 * j + 1]
                + cw[o * 4 + 3] * xs[2 * j + 3];
        z[o * 20 + j] = fmaxf(v, 0.f);
    }
    __syncthreads();

    for (int idx = tid; idx < FEAT; idx += 128) {
        int o = idx / 19, j = idx % 19;
        float v = fmaxf(z[o * 20 + j], z[o * 20 + j + 1]);
        split_pair(v, g_feath[(size_t)s * FEAT + idx], g_featl[(size_t)s * FEAT + idx]);
    }
}

// conv2(k=2,2->32) + relu + pool3 -> y pair; one block per sample, no divides
__global__ __launch_bounds__(256)
void conv2pool_kernel(const float* __restrict__ w2, const float* __restrict__ b2)
{
    __shared__ float slo[HF], sro[HF], sw[128], sb[32];
    const int n = blockIdx.x;
    const int tid = threadIdx.x;
    const int wid = tid >> 5;
    const int lane = tid & 31;
    for (int i = tid; i < HF; i += 256) {
        slo[i] = g_both[(size_t)n * HF + i];
        sro[i] = g_both[(size_t)(NB + n) * HF + i];
    }
    if (tid < 128) sw[tid] = w2[tid];
    if (tid < 32)  sb[tid] = b2[tid];
    __syncthreads();

    for (int o = wid; o < 32; o += 8) {
        const float w00 = sw[o * 4 + 0], w01 = sw[o * 4 + 1];
        const float w10 = sw[o * 4 + 2], w11 = sw[o * 4 + 3];
        const float bb = sb[o];
        const size_t obase = (size_t)n * YK + o * 297;
        for (int jj = lane; jj < 297; jj += 32) {
            float l0 = slo[jj], l1 = slo[jj + 1], l2v = slo[jj + 2], l3 = slo[jj + 3];
            float r0 = sro[jj], r1 = sro[jj + 1], r2v = sro[jj + 2], r3 = sro[jj + 3];
            float z0 = bb + w00 * l0  + w01 * l1  + w10 * r0  + w11 * r1;
            float z1 = bb + w00 * l1  + w01 * l2v + w10 * r1  + w11 * r2v;
            float z2 = bb + w00 * l2v + w01 * l3  + w10 * r2v + w11 * r3;
            float v = fmaxf(fmaxf(z0, z1), fmaxf(z2, 0.f));
            split_pair(v, g_yh[obase + jj], g_yl[obase + jj]);
        }
    }
}

// final: hidden = sum(hpart); i2h = sum(part)+l2b; out = relu((i2h+hidden)@ow^T+ob)
__global__ __launch_bounds__(512)
void out_kernel(const float* __restrict__ part,
                const float* __restrict__ hpart,
                const float* __restrict__ l2b,
                const float* __restrict__ ow,
                const float* __restrict__ ob,
                float* __restrict__ out,
                float* __restrict__ hidOut)
{
    __shared__ float val[HID];
    const int n   = blockIdx.x;
    const int tid = threadIdx.x;

    if (tid < HID) {
        const size_t o = (size_t)n * HID + tid;
        float hs = hpart[o];
        #pragma unroll
        for (int s = 1; s < CHS; ++s) hs += hpart[(size_t)s * NB * HID + o];
        float is = l2b[tid];
        #pragma unroll
        for (int s = 0; s < L2S; ++s) is += part[(size_t)s * NB * HID + o];
        hidOut[o] = hs;
        val[tid] = hs + is;
    }
    __syncthreads();

    if (tid < OUT * 32) {
        const int m    = tid >> 5;
        const int lane = tid & 31;
        const float* w = ow + (size_t)m * HID;
        float s = 0.f;
        for (int k = lane; k < HID; k += 32) s += val[k] * w[k];
        #pragma unroll
        for (int o = 16; o; o >>= 1) s += __shfl_down_sync(0xffffffffu, s, o);
        if (lane == 0) out[n * OUT + m] = fmaxf(s + ob[m], 0.f);
    }
}

// ---------------------------------------------------------------------------
static cudaStream_t s_side = nullptr;
static cudaStream_t s_w    = nullptr;
static cudaEvent_t  s_evF  = nullptr;
static cudaEvent_t  s_evW  = nullptr;
static cudaEvent_t  s_evJ  = nullptr;

extern "C" void kernel_launch(void* const* d_in, const int* in_sizes, int n_in,
                              void* d_out, int out_size)
{
    if (!s_side) {
        cudaStreamCreateWithFlags(&s_side, cudaStreamNonBlocking);
        cudaStreamCreateWithFlags(&s_w, cudaStreamNonBlocking);
        cudaEventCreateWithFlags(&s_evF, cudaEventDisableTiming);
        cudaEventCreateWithFlags(&s_evW, cudaEventDisableTiming);
        cudaEventCreateWithFlags(&s_evJ, cudaEventDisableTiming);
    }

    const float* hand_data = (const float*)d_in[0];
    const float* hidden    = (const float*)d_in[1];
    const float* l_conv_w  = (const float*)d_in[2];
    const float* l_conv_b  = (const float*)d_in[3];
    const float* l_fc_w    = (const float*)d_in[4];
    const float* l_fc_b    = (const float*)d_in[5];
    const float* r_conv_w  = (const float*)d_in[6];
    const float* r_conv_b  = (const float*)d_in[7];
    const float* r_fc_w    = (const float*)d_in[8];
    const float* r_fc_b    = (const float*)d_in[9];
    const float* conv2_w   = (const float*)d_in[10];
    const float* conv2_b   = (const float*)d_in[11];
    const float* l2_w      = (const float*)d_in[12];
    const float* l2_b      = (const float*)d_in[13];
    const float* h2h_w     = (const float*)d_in[14];
    const float* h2h_b     = (const float*)d_in[15];
    const float* out_w     = (const float*)d_in[16];
    const float* out_b     = (const float*)d_in[17];

    const int T    = in_sizes[0] / (NB * 84);
    const int tOff = (T - 1) * NB * 84;

    bf *feath, *featl, *yh, *yl, *l2wh, *l2wl;
    bf *Wh, *Wl, *WTh, *WTl, *M0h, *M0l, *M0Th, *M0Tl, *M1h, *M1l, *M1Th, *M1Tl;
    bf *h0h, *h0l;
    float *part, *cpart, *hpart, *hid;
    cudaGetSymbolAddress((void**)&feath, g_feath);
    cudaGetSymbolAddress((void**)&featl, g_featl);
    cudaGetSymbolAddress((void**)&yh,    g_yh);
    cudaGetSymbolAddress((void**)&yl,    g_yl);
    cudaGetSymbolAddress((void**)&l2wh,  g_l2wh);
    cudaGetSymbolAddress((void**)&l2wl,  g_l2wl);
    cudaGetSymbolAddress((void**)&part,  g_part);
    cudaGetSymbolAddress((void**)&cpart, g_cpart);
    cudaGetSymbolAddress((void**)&hpart, g_hpart);
    cudaGetSymbolAddress((void**)&Wh,    g_Wh);
    cudaGetSymbolAddress((void**)&Wl,    g_Wl);
    cudaGetSymbolAddress((void**)&WTh,   g_WTh);
    cudaGetSymbolAddress((void**)&WTl,   g_WTl);
    cudaGetSymbolAddress((void**)&M0h,   g_M0h);
    cudaGetSymbolAddress((void**)&M0l,   g_M0l);
    cudaGetSymbolAddress((void**)&M0Th,  g_M0Th);
    cudaGetSymbolAddress((void**)&M0Tl,  g_M0Tl);
    cudaGetSymbolAddress((void**)&M1h,   g_M1h);
    cudaGetSymbolAddress((void**)&M1l,   g_M1l);
    cudaGetSymbolAddress((void**)&M1Th,  g_M1Th);
    cudaGetSymbolAddress((void**)&M1Tl,  g_M1Tl);
    cudaGetSymbolAddress((void**)&h0h,   g_h0h);
    cudaGetSymbolAddress((void**)&h0l,   g_h0l);
    cudaGetSymbolAddress((void**)&hid,   g_hid);

    float* both;
    cudaGetSymbolAddress((void**)&both, g_both);
    float* hidOut = (out_size >= NB * OUT + NB * HID) ? ((float*)d_out) + NB * OUT : hid;

    // fork both helper streams off the main stream head
    cudaEventRecord(s_evF, 0);
    cudaStreamWaitEvent(s_side, s_evF, 0);
    cudaStreamWaitEvent(s_w, s_evF, 0);

    // ---- side stream: pad -> 5x (split-K squaring + reduce) -> hidden partials
    pad_kernel<<<(HIDP * HIDP + 255) / 256, 256, 0, s_side>>>(h2h_w, h2h_b, hidden);
    {
        const bf *sh = Wh, *sl = Wl, *sth = WTh, *stl = WTl;
        bf* dh [5] = { M0h,  M1h,  M0h,  M1h,  M0h  };
        bf* dl [5] = { M0l,  M1l,  M0l,  M1l,  M0l  };
        bf* dth[5] = { M0Th, M1Th, M0Th, M1Th, M0Th };
        bf* dtl[5] = { M0Tl, M1Tl, M0Tl, M1Tl, M0Tl };
        for (int i = 0; i < 5; ++i) {
            pp_gemm<true><<<dim3(8, 8, CHS), 256, 0, s_side>>>(
                HIDP, HIDP, HIDP, sh, sl, HIDP, sth, stl, HIDP, cpart, HIDP, CHLEN);
            if (i < 4)
                reduce_split<true><<<dim3(16, 16), 256, 0, s_side>>>(
                    cpart, dh[i], dl[i], dth[i], dtl[i]);
            else
                reduce_split<false><<<dim3(16, 16), 256, 0, s_side>>>(
                    cpart, dh[i], dl[i], nullptr, nullptr);
            sh = dh[i]; sl = dl[i]; sth = dth[i]; stl = dtl[i];
        }
        // hidden partials = h0aug @ M32^T  (bias via homogeneous column)
        pp_gemm<true><<<dim3(8, 8, CHS), 256, 0, s_side>>>(
            NB, HID, HIDP, h0h, h0l, HIDP, M0h, M0l, HIDP, hpart, HID, CHLEN);
    }
    cudaEventRecord(s_evJ, s_side);

    // ---- weight-split stream
    split_w_kernel<<<(HIDP * YK / 4 + 255) / 256, 256, 0, s_w>>>(l2_w);
    cudaEventRecord(s_evW, s_w);

    // ---- main stream: data front-end
    hand_feat_kernel<<<1024, 128>>>(hand_data, l_conv_w, l_conv_b, r_conv_w, r_conv_b, tOff);
    fc_gemm<<<dim3(5, 16), 256>>>(feath, featl, l_fc_w, l_fc_b, r_fc_w, r_fc_b, both);
    conv2pool_kernel<<<NB, 256>>>(conv2_w, conv2_b);
    cudaStreamWaitEvent(0, s_evW, 0);
    pp_gemm<true><<<dim3(8, 8, L2S), 256>>>(
        NB, HID, YK, yh, yl, YK, l2wh, l2wl, YK, part, HID, L2LEN);

    // ---- join + final fused kernel
    cudaStreamWaitEvent(0, s_evJ, 0);
    out_kernel<<<NB, 512>>>(part, hpart, l2_b, out_w, out_b, (float*)d_out, hidOut);
}